// round 1
// baseline (speedup 1.0000x reference)
#include <cuda_runtime.h>
#include <math.h>

// Problem constants
#define N_INST 16384
#define BAGS   64
#define NMC    4
#define RF     512
#define D0     1024
#define D1     512
#define D2     256
#define NATT   4
#define DATT   32

// ---------------------------------------------------------------------------
// Scratch (static device globals: allocation-guard safe)
// ---------------------------------------------------------------------------
__device__ float g_z  [(size_t)NMC * N_INST * RF];       // z1 / z2 / emb_new (reused)
__device__ float g_phi[(size_t)NMC * N_INST * 2 * RF];   // phi1 / phi2
__device__ float g_h1 [(size_t)NMC * N_INST * D1];
__device__ float g_emb[(size_t)NMC * N_INST * D2];
__device__ float g_expP[(size_t)N_INST * NMC * NATT];
__device__ float g_seg [BAGS * NMC * NATT];

// ---------------------------------------------------------------------------
// Generic batched SGEMM: C[M,N] = A[M,K] @ B[K,N] (+ bias), all row-major.
// Tiles: 128x128x8, 256 threads, 8x8 micro-tile per thread, float4 I/O.
// All problem shapes divide the tiles exactly -> no bounds checks.
// ---------------------------------------------------------------------------
#define BM 128
#define BN 128
#define BK 8
#define TM 8
#define TN 8

__global__ __launch_bounds__(256) void sgemm_kernel(
    const float* __restrict__ A, const float* __restrict__ B,
    const float* __restrict__ bias, float* __restrict__ C,
    int M, int Ncols, int K,
    long long sA, long long sB, long long sC)
{
    A += (long long)blockIdx.z * sA;
    B += (long long)blockIdx.z * sB;
    C += (long long)blockIdx.z * sC;

    __shared__ float As[BK][BM];
    __shared__ float Bs[BK][BN];

    const int tid  = threadIdx.x;
    const int brow = blockIdx.y * BM;
    const int bcol = blockIdx.x * BN;

    // A tile load: 128 rows x 8 cols -> 256 float4 (one per thread)
    const int aRow = tid >> 1;
    const int aCol = (tid & 1) * 4;
    // B tile load: 8 rows x 128 cols -> 256 float4
    const int bRow = tid >> 5;
    const int bCol = (tid & 31) * 4;

    const int trow = (tid >> 4) * TM;
    const int tcol = (tid & 15) * TN;

    float acc[TM][TN];
#pragma unroll
    for (int i = 0; i < TM; i++)
#pragma unroll
        for (int j = 0; j < TN; j++) acc[i][j] = 0.f;

    const float* Aptr = A + (long long)(brow + aRow) * K + aCol;
    const float* Bptr = B + (long long)bRow * Ncols + bcol + bCol;

    for (int k0 = 0; k0 < K; k0 += BK) {
        float4 a4 = *(const float4*)(Aptr + k0);
        As[aCol + 0][aRow] = a4.x;
        As[aCol + 1][aRow] = a4.y;
        As[aCol + 2][aRow] = a4.z;
        As[aCol + 3][aRow] = a4.w;
        float4 b4 = *(const float4*)(Bptr + (long long)k0 * Ncols);
        *(float4*)(&Bs[bRow][bCol]) = b4;
        __syncthreads();
#pragma unroll
        for (int k = 0; k < BK; k++) {
            float ar[TM], br[TN];
#pragma unroll
            for (int i = 0; i < TM; i++) ar[i] = As[k][trow + i];
#pragma unroll
            for (int j = 0; j < TN; j++) br[j] = Bs[k][tcol + j];
#pragma unroll
            for (int i = 0; i < TM; i++)
#pragma unroll
                for (int j = 0; j < TN; j++)
                    acc[i][j] = fmaf(ar[i], br[j], acc[i][j]);
        }
        __syncthreads();
    }

    float bv[TN];
#pragma unroll
    for (int j = 0; j < TN; j++) bv[j] = bias ? bias[bcol + tcol + j] : 0.f;

#pragma unroll
    for (int i = 0; i < TM; i++) {
        float* crow = C + (long long)(brow + trow + i) * Ncols + bcol + tcol;
#pragma unroll
        for (int j = 0; j < TN; j += 4) {
            float4 v;
            v.x = acc[i][j + 0] + bv[j + 0];
            v.y = acc[i][j + 1] + bv[j + 1];
            v.z = acc[i][j + 2] + bv[j + 2];
            v.w = acc[i][j + 3] + bv[j + 3];
            *(float4*)(crow + j) = v;
        }
    }
}

// ---------------------------------------------------------------------------
// Fused RBF random features + LayerNorm.
// Input row z[RF=512] -> phi[2RF=1024] = LN( concat(cos z, sin z) / sqrt(RF) ).
// One 256-thread block per row; thread t handles z[t], z[t+256].
// ---------------------------------------------------------------------------
__global__ __launch_bounds__(256) void rfln_kernel(
    const float* __restrict__ z, float* __restrict__ phi)
{
    const long long row = blockIdx.x;
    const float* zr = z + row * RF;
    float* pr = phi + row * (2 * RF);
    const int t = threadIdx.x;
    const float scale = 0.044194173824159216f;  // 1/sqrt(512)

    float za = zr[t];
    float zb = zr[t + 256];
    float sa, ca, sb, cb;
    sincosf(za, &sa, &ca);
    sincosf(zb, &sb, &cb);
    ca *= scale; sa *= scale; cb *= scale; sb *= scale;

    float sum = ca + cb + sa + sb;
    float sq  = ca * ca + cb * cb + sa * sa + sb * sb;

#pragma unroll
    for (int o = 16; o > 0; o >>= 1) {
        sum += __shfl_down_sync(0xffffffffu, sum, o);
        sq  += __shfl_down_sync(0xffffffffu, sq,  o);
    }
    __shared__ float s_sum[8], s_sq[8];
    __shared__ float s_mean, s_inv;
    const int warp = t >> 5, lane = t & 31;
    if (lane == 0) { s_sum[warp] = sum; s_sq[warp] = sq; }
    __syncthreads();
    if (t == 0) {
        float ts = 0.f, tq = 0.f;
#pragma unroll
        for (int i = 0; i < 8; i++) { ts += s_sum[i]; tq += s_sq[i]; }
        float mean = ts * (1.f / 1024.f);
        float var  = tq * (1.f / 1024.f) - mean * mean;
        s_mean = mean;
        s_inv  = rsqrtf(var + 1e-5f);
    }
    __syncthreads();
    const float mean = s_mean, inv = s_inv;
    pr[t]       = (ca - mean) * inv;
    pr[t + 256] = (cb - mean) * inv;
    pr[t + 512] = (sa - mean) * inv;
    pr[t + 768] = (sb - mean) * inv;
}

// ---------------------------------------------------------------------------
// Attention scores: per (m,n), 4 dots of length 256; exp(score/16);
// per-bag segment sums via atomics.
// One warp per (m,n) row.
// ---------------------------------------------------------------------------
__global__ __launch_bounds__(256) void scores_kernel(
    const float* __restrict__ emb, const float* __restrict__ Ws,
    const float* __restrict__ bs, const int* __restrict__ idx,
    float* __restrict__ expP, float* __restrict__ seg)
{
    const int gw   = (blockIdx.x * blockDim.x + threadIdx.x) >> 5;
    const int lane = threadIdx.x & 31;
    if (gw >= NMC * N_INST) return;
    const int m = gw / N_INST;
    const int n = gw - m * N_INST;
    const float* e = emb + (long long)gw * D2;

    float a0 = 0.f, a1 = 0.f, a2 = 0.f, a3 = 0.f;
    for (int d = lane; d < D2; d += 32) {
        float  ev = e[d];
        float4 w4 = *(const float4*)(Ws + d * 4);
        a0 = fmaf(ev, w4.x, a0);
        a1 = fmaf(ev, w4.y, a1);
        a2 = fmaf(ev, w4.z, a2);
        a3 = fmaf(ev, w4.w, a3);
    }
#pragma unroll
    for (int o = 16; o > 0; o >>= 1) {
        a0 += __shfl_down_sync(0xffffffffu, a0, o);
        a1 += __shfl_down_sync(0xffffffffu, a1, o);
        a2 += __shfl_down_sync(0xffffffffu, a2, o);
        a3 += __shfl_down_sync(0xffffffffu, a3, o);
    }
    if (lane == 0) {
        const int b = idx[n];
        const float inv16 = 0.0625f;  // 1/sqrt(D2)
        float v0 = expf((a0 + bs[0]) * inv16);
        float v1 = expf((a1 + bs[1]) * inv16);
        float v2 = expf((a2 + bs[2]) * inv16);
        float v3 = expf((a3 + bs[3]) * inv16);
        float* ep = expP + ((long long)n * NMC + m) * NATT;
        ep[0] = v0; ep[1] = v1; ep[2] = v2; ep[3] = v3;
        float* sp = seg + ((long long)b * NMC + m) * NATT;
        atomicAdd(sp + 0, v0);
        atomicAdd(sp + 1, v1);
        atomicAdd(sp + 2, v2);
        atomicAdd(sp + 3, v3);
    }
}

// ---------------------------------------------------------------------------
// Weighted segment pooling: out[b,m,e] += relu(emb_new[m,n,e]) * prob[n,m,e/32].
// Block = 128 threads (one per e), processes 8 consecutive n rows; register
// accumulation across rows sharing the same bag (X_idx is sorted) before the
// atomicAdd flush.
// ---------------------------------------------------------------------------
__global__ __launch_bounds__(128) void pool_kernel(
    const float* __restrict__ embnew, const float* __restrict__ expP,
    const float* __restrict__ seg, const int* __restrict__ idx,
    float* __restrict__ out)
{
    const int m  = blockIdx.y;
    const int n0 = blockIdx.x * 8;
    const int e  = threadIdx.x;     // 0..127
    const int k  = e >> 5;          // which attention head

    float accum = 0.f;
    int   cur   = -1;
#pragma unroll
    for (int r = 0; r < 8; r++) {
        const int n = n0 + r;
        const int b = idx[n];
        float v = embnew[((long long)m * N_INST + n) * (NATT * DATT) + e];
        v = fmaxf(v, 0.f);
        const float p = expP[((long long)n * NMC + m) * NATT + k] /
                        seg [((long long)b * NMC + m) * NATT + k];
        v *= p;
        if (b != cur) {
            if (cur >= 0) atomicAdd(out + ((long long)cur * NMC + m) * (NATT * DATT) + e, accum);
            cur = b;
            accum = v;
        } else {
            accum += v;
        }
    }
    if (cur >= 0) atomicAdd(out + ((long long)cur * NMC + m) * (NATT * DATT) + e, accum);
}

// ---------------------------------------------------------------------------
__global__ void zero_kernel(float* __restrict__ out, float* __restrict__ seg)
{
    const int i = blockIdx.x * blockDim.x + threadIdx.x;
    if (i < BAGS * NMC * NATT * DATT) out[i] = 0.f;
    if (i < BAGS * NMC * NATT)        seg[i] = 0.f;
}

// ---------------------------------------------------------------------------
extern "C" void kernel_launch(void* const* d_in, const int* in_sizes, int n_in,
                              void* d_out, int out_size)
{
    const float* X      = (const float*)d_in[0];
    const int*   X_idx  = (const int*)  d_in[1];
    const float* Omega1 = (const float*)d_in[2];
    const float* Omega2 = (const float*)d_in[3];
    const float* W1     = (const float*)d_in[4];
    const float* b1     = (const float*)d_in[5];
    const float* W2     = (const float*)d_in[6];
    const float* b2     = (const float*)d_in[7];
    const float* Ws     = (const float*)d_in[8];
    const float* bs     = (const float*)d_in[9];
    const float* Wm     = (const float*)d_in[10];
    const float* bm     = (const float*)d_in[11];
    float* out = (float*)d_out;

    float *z, *phi, *h1, *emb, *expP, *seg;
    cudaGetSymbolAddress((void**)&z,    g_z);
    cudaGetSymbolAddress((void**)&phi,  g_phi);
    cudaGetSymbolAddress((void**)&h1,   g_h1);
    cudaGetSymbolAddress((void**)&emb,  g_emb);
    cudaGetSymbolAddress((void**)&expP, g_expP);
    cudaGetSymbolAddress((void**)&seg,  g_seg);

    // 0. zero accumulators (d_out is poisoned by harness)
    zero_kernel<<<128, 256>>>(out, seg);

    // 1. z1[m] = X @ Omega1[m]                [16384,1024]x[1024,512], batched over m
    {
        dim3 g(RF / BN, N_INST / BM, NMC);
        sgemm_kernel<<<g, 256>>>(X, Omega1, nullptr, z,
                                 N_INST, RF, D0,
                                 0LL, (long long)D0 * RF, (long long)N_INST * RF);
    }
    // 2. phi1 = LN(rf(z1))
    rfln_kernel<<<NMC * N_INST, 256>>>(z, phi);

    // 3. h1 = phi1 @ W1 + b1                  [65536,1024]x[1024,512]
    {
        dim3 g(D1 / BN, (NMC * N_INST) / BM, 1);
        sgemm_kernel<<<g, 256>>>(phi, W1, b1, h1,
                                 NMC * N_INST, D1, 2 * RF, 0LL, 0LL, 0LL);
    }
    // 4. z2[m] = h1[m] @ Omega2[m]            [16384,512]x[512,512], batched
    {
        dim3 g(RF / BN, N_INST / BM, NMC);
        sgemm_kernel<<<g, 256>>>(h1, Omega2, nullptr, z,
                                 N_INST, RF, D1,
                                 (long long)N_INST * D1, (long long)D1 * RF,
                                 (long long)N_INST * RF);
    }
    // 5. phi2 = LN(rf(z2))
    rfln_kernel<<<NMC * N_INST, 256>>>(z, phi);

    // 6. emb = phi2 @ W2 + b2                 [65536,1024]x[1024,256]
    {
        dim3 g(D2 / BN, (NMC * N_INST) / BM, 1);
        sgemm_kernel<<<g, 256>>>(phi, W2, b2, emb,
                                 NMC * N_INST, D2, 2 * RF, 0LL, 0LL, 0LL);
    }
    // 7. attention scores + segment exp-sums
    scores_kernel<<<(NMC * N_INST * 32 + 255) / 256, 256>>>(emb, Ws, bs, X_idx, expP, seg);

    // 8. emb_new = emb @ Wm + bm              [65536,256]x[256,128] (into z scratch)
    {
        dim3 g((NATT * DATT) / BN, (NMC * N_INST) / BM, 1);
        sgemm_kernel<<<g, 256>>>(emb, Wm, bm, z,
                                 NMC * N_INST, NATT * DATT, D2, 0LL, 0LL, 0LL);
    }
    // 9. relu + softmax weighting + segment pooling
    pool_kernel<<<dim3(N_INST / 8, NMC), 128>>>(z, expP, seg, X_idx, out);
}

// round 2
// speedup vs baseline: 1.3905x; 1.3905x over previous
#include <cuda_runtime.h>
#include <math.h>
#include <stdint.h>

// Problem constants
#define N_INST 16384
#define BAGS   64
#define NMC    4
#define RF     512
#define D0     1024
#define D1     512
#define D2     256
#define NATT   4
#define DATT   32

// ---------------------------------------------------------------------------
// Scratch (static device globals: allocation-guard safe)
// ---------------------------------------------------------------------------
__device__ float g_z  [(size_t)NMC * N_INST * RF];       // z1 / z2 / emb_new (reused)
__device__ float g_phi[(size_t)NMC * N_INST * 2 * RF];   // phi1 / phi2
__device__ float g_h1 [(size_t)NMC * N_INST * D1];
__device__ float g_emb[(size_t)NMC * N_INST * D2];
__device__ float g_expP[(size_t)N_INST * NMC * NATT];
__device__ float g_seg [BAGS * NMC * NATT];

// ---------------------------------------------------------------------------
// 3xTF32 tensor-core GEMM: C[M,N] = A[M,K] @ B[K,N] (+bias), row-major.
// Block tile 128x128x16, 256 threads (8 warps), warp tile 32x64.
// Each fp32 operand split hi/lo in tf32; 3 MMA terms -> ~1e-7 rounding.
// cp.async double-buffered smem; padded layouts are LDS-conflict-free.
// ---------------------------------------------------------------------------
#define TBM 128
#define TBN 128
#define TBK 16
#define ALD 20    // As row stride (floats): conflict-free for frag reads
#define BLD 136   // Bs row stride (floats): +8 pad, conflict-free

#define CP_ASYNC16(smem_u32, gptr) \
    asm volatile("cp.async.cg.shared.global [%0], [%1], 16;\n" \
                 :: "r"(smem_u32), "l"(gptr))
#define CP_COMMIT()  asm volatile("cp.async.commit_group;\n")
#define CP_WAIT(n)   asm volatile("cp.async.wait_group %0;\n" :: "n"(n))

__device__ __forceinline__ void tf32_split(float x, uint32_t& hi, uint32_t& lo) {
    asm("cvt.rna.tf32.f32 %0, %1;" : "=r"(hi) : "f"(x));
    float r = x - __uint_as_float(hi);
    asm("cvt.rna.tf32.f32 %0, %1;" : "=r"(lo) : "f"(r));
}

#define MMA_TF32(c, a, b) \
    asm volatile("mma.sync.aligned.m16n8k8.row.col.f32.tf32.tf32.f32 " \
                 "{%0,%1,%2,%3}, {%4,%5,%6,%7}, {%8,%9}, {%0,%1,%2,%3};" \
                 : "+f"((c)[0]), "+f"((c)[1]), "+f"((c)[2]), "+f"((c)[3]) \
                 : "r"((a)[0]), "r"((a)[1]), "r"((a)[2]), "r"((a)[3]), \
                   "r"((b)[0]), "r"((b)[1]))

__global__ __launch_bounds__(256, 1) void tf32x3_gemm(
    const float* __restrict__ A, const float* __restrict__ B,
    const float* __restrict__ bias, float* __restrict__ C,
    int M, int Ncols, int K,
    long long sA, long long sB, long long sC)
{
    A += (long long)blockIdx.z * sA;
    B += (long long)blockIdx.z * sB;
    C += (long long)blockIdx.z * sC;

    __shared__ float As[2][TBM * ALD];
    __shared__ float Bs[2][TBK * BLD];

    const int tid  = threadIdx.x;
    const int wid  = tid >> 5;
    const int lane = tid & 31;
    const int wm   = (wid >> 1) * 32;   // warp m offset (4 warp-rows)
    const int wn   = (wid & 1) * 64;    // warp n offset (2 warp-cols)
    const int brow = blockIdx.y * TBM;
    const int bcol = blockIdx.x * TBN;

    const int lg   = lane >> 2;         // 0..7
    const int lq   = lane & 3;          // 0..3

    float acc[2][8][4];
#pragma unroll
    for (int mi = 0; mi < 2; mi++)
#pragma unroll
        for (int ni = 0; ni < 8; ni++)
#pragma unroll
            for (int j = 0; j < 4; j++) acc[mi][ni][j] = 0.f;

    const int nStages = K / TBK;

    uint32_t asAddr = (uint32_t)__cvta_generic_to_shared(&As[0][0]);
    uint32_t bsAddr = (uint32_t)__cvta_generic_to_shared(&Bs[0][0]);
    const uint32_t asStride = TBM * ALD * 4;
    const uint32_t bsStride = TBK * BLD * 4;

    // Per-thread staging coordinates
    const int aR  = tid >> 1;              // A: idx = tid*2+i -> same row, cols {0,4} or {8,12}
    const int aC0 = (tid & 1) * 8;
    const int bR  = tid >> 4;              // B: idx = tid*2+i -> same row, cols (tid&15)*8 + {0,4}
    const int bC0 = (tid & 15) * 8;

    // prologue: stage 0
    {
#pragma unroll
        for (int i = 0; i < 2; i++) {
            const float* gp = A + (long long)(brow + aR) * K + aC0 + i * 4;
            CP_ASYNC16(asAddr + (aR * ALD + aC0 + i * 4) * 4, gp);
        }
#pragma unroll
        for (int i = 0; i < 2; i++) {
            const float* gp = B + (long long)bR * Ncols + bcol + bC0 + i * 4;
            CP_ASYNC16(bsAddr + (bR * BLD + bC0 + i * 4) * 4, gp);
        }
        CP_COMMIT();
    }

    for (int s = 0; s < nStages; s++) {
        const int buf = s & 1;
        if (s + 1 < nStages) {
            const int k0 = (s + 1) * TBK;
            const uint32_t asb = asAddr + (buf ^ 1) * asStride;
            const uint32_t bsb = bsAddr + (buf ^ 1) * bsStride;
#pragma unroll
            for (int i = 0; i < 2; i++) {
                const float* gp = A + (long long)(brow + aR) * K + k0 + aC0 + i * 4;
                CP_ASYNC16(asb + (aR * ALD + aC0 + i * 4) * 4, gp);
            }
#pragma unroll
            for (int i = 0; i < 2; i++) {
                const float* gp = B + (long long)(k0 + bR) * Ncols + bcol + bC0 + i * 4;
                CP_ASYNC16(bsb + (bR * BLD + bC0 + i * 4) * 4, gp);
            }
            CP_COMMIT();
            CP_WAIT(1);
        } else {
            CP_WAIT(0);
        }
        __syncthreads();

        const float* __restrict__ asb = &As[buf][0];
        const float* __restrict__ bsb = &Bs[buf][0];

#pragma unroll
        for (int kk = 0; kk < 2; kk++) {
            const int k0 = kk * 8;
            uint32_t Ah[2][4], Al[2][4], Bh[8][2], Bl[8][2];
#pragma unroll
            for (int mi = 0; mi < 2; mi++) {
                const int r = wm + mi * 16 + lg;
                const int c = k0 + lq;
                float a0 = asb[r * ALD + c];
                float a1 = asb[(r + 8) * ALD + c];
                float a2 = asb[r * ALD + c + 4];
                float a3 = asb[(r + 8) * ALD + c + 4];
                tf32_split(a0, Ah[mi][0], Al[mi][0]);
                tf32_split(a1, Ah[mi][1], Al[mi][1]);
                tf32_split(a2, Ah[mi][2], Al[mi][2]);
                tf32_split(a3, Ah[mi][3], Al[mi][3]);
            }
#pragma unroll
            for (int ni = 0; ni < 8; ni++) {
                const int n  = wn + ni * 8 + lg;
                const int kr = k0 + lq;
                float b0 = bsb[kr * BLD + n];
                float b1 = bsb[(kr + 4) * BLD + n];
                tf32_split(b0, Bh[ni][0], Bl[ni][0]);
                tf32_split(b1, Bh[ni][1], Bl[ni][1]);
            }
#pragma unroll
            for (int mi = 0; mi < 2; mi++)
#pragma unroll
                for (int ni = 0; ni < 8; ni++) {
                    MMA_TF32(acc[mi][ni], Ah[mi], Bh[ni]);
                    MMA_TF32(acc[mi][ni], Al[mi], Bh[ni]);
                    MMA_TF32(acc[mi][ni], Ah[mi], Bl[ni]);
                }
        }
        __syncthreads();
    }

    // Epilogue
#pragma unroll
    for (int mi = 0; mi < 2; mi++) {
        const int row0 = brow + wm + mi * 16 + lg;
#pragma unroll
        for (int ni = 0; ni < 8; ni++) {
            const int col = bcol + wn + ni * 8 + lq * 2;
            float b0 = 0.f, b1 = 0.f;
            if (bias) { b0 = bias[col]; b1 = bias[col + 1]; }
            float2 v0 = make_float2(acc[mi][ni][0] + b0, acc[mi][ni][1] + b1);
            float2 v1 = make_float2(acc[mi][ni][2] + b0, acc[mi][ni][3] + b1);
            *(float2*)(C + (long long)row0 * Ncols + col)       = v0;
            *(float2*)(C + (long long)(row0 + 8) * Ncols + col) = v1;
        }
    }
}

// ---------------------------------------------------------------------------
// Fused RBF random features + LayerNorm (MUFU sin/cos).
// ---------------------------------------------------------------------------
__global__ __launch_bounds__(256) void rfln_kernel(
    const float* __restrict__ z, float* __restrict__ phi)
{
    const long long row = blockIdx.x;
    const float* zr = z + row * RF;
    float* pr = phi + row * (2 * RF);
    const int t = threadIdx.x;
    const float scale = 0.044194173824159216f;  // 1/sqrt(512)

    float za = zr[t];
    float zb = zr[t + 256];
    float ca = __cosf(za) * scale;
    float sa = __sinf(za) * scale;
    float cb = __cosf(zb) * scale;
    float sb = __sinf(zb) * scale;

    float sum = ca + cb + sa + sb;
    float sq  = ca * ca + cb * cb + sa * sa + sb * sb;

#pragma unroll
    for (int o = 16; o > 0; o >>= 1) {
        sum += __shfl_down_sync(0xffffffffu, sum, o);
        sq  += __shfl_down_sync(0xffffffffu, sq,  o);
    }
    __shared__ float s_sum[8], s_sq[8];
    __shared__ float s_mean, s_inv;
    const int warp = t >> 5, lane = t & 31;
    if (lane == 0) { s_sum[warp] = sum; s_sq[warp] = sq; }
    __syncthreads();
    if (t == 0) {
        float ts = 0.f, tq = 0.f;
#pragma unroll
        for (int i = 0; i < 8; i++) { ts += s_sum[i]; tq += s_sq[i]; }
        float mean = ts * (1.f / 1024.f);
        float var  = tq * (1.f / 1024.f) - mean * mean;
        s_mean = mean;
        s_inv  = rsqrtf(var + 1e-5f);
    }
    __syncthreads();
    const float mean = s_mean, inv = s_inv;
    pr[t]       = (ca - mean) * inv;
    pr[t + 256] = (cb - mean) * inv;
    pr[t + 512] = (sa - mean) * inv;
    pr[t + 768] = (sb - mean) * inv;
}

// ---------------------------------------------------------------------------
// Attention scores + per-bag exp-sum (atomics).
// ---------------------------------------------------------------------------
__global__ __launch_bounds__(256) void scores_kernel(
    const float* __restrict__ emb, const float* __restrict__ Ws,
    const float* __restrict__ bs, const int* __restrict__ idx,
    float* __restrict__ expP, float* __restrict__ seg)
{
    const int gw   = (blockIdx.x * blockDim.x + threadIdx.x) >> 5;
    const int lane = threadIdx.x & 31;
    if (gw >= NMC * N_INST) return;
    const int m = gw / N_INST;
    const int n = gw - m * N_INST;
    const float* e = emb + (long long)gw * D2;

    float a0 = 0.f, a1 = 0.f, a2 = 0.f, a3 = 0.f;
    for (int d = lane; d < D2; d += 32) {
        float  ev = e[d];
        float4 w4 = *(const float4*)(Ws + d * 4);
        a0 = fmaf(ev, w4.x, a0);
        a1 = fmaf(ev, w4.y, a1);
        a2 = fmaf(ev, w4.z, a2);
        a3 = fmaf(ev, w4.w, a3);
    }
#pragma unroll
    for (int o = 16; o > 0; o >>= 1) {
        a0 += __shfl_down_sync(0xffffffffu, a0, o);
        a1 += __shfl_down_sync(0xffffffffu, a1, o);
        a2 += __shfl_down_sync(0xffffffffu, a2, o);
        a3 += __shfl_down_sync(0xffffffffu, a3, o);
    }
    if (lane == 0) {
        const int b = idx[n];
        const float inv16 = 0.0625f;  // 1/sqrt(D2)
        float v0 = expf((a0 + bs[0]) * inv16);
        float v1 = expf((a1 + bs[1]) * inv16);
        float v2 = expf((a2 + bs[2]) * inv16);
        float v3 = expf((a3 + bs[3]) * inv16);
        float* ep = expP + ((long long)n * NMC + m) * NATT;
        ep[0] = v0; ep[1] = v1; ep[2] = v2; ep[3] = v3;
        float* sp = seg + ((long long)b * NMC + m) * NATT;
        atomicAdd(sp + 0, v0);
        atomicAdd(sp + 1, v1);
        atomicAdd(sp + 2, v2);
        atomicAdd(sp + 3, v3);
    }
}

// ---------------------------------------------------------------------------
// Weighted segment pooling.
// ---------------------------------------------------------------------------
__global__ __launch_bounds__(128) void pool_kernel(
    const float* __restrict__ embnew, const float* __restrict__ expP,
    const float* __restrict__ seg, const int* __restrict__ idx,
    float* __restrict__ out)
{
    const int m  = blockIdx.y;
    const int n0 = blockIdx.x * 8;
    const int e  = threadIdx.x;
    const int k  = e >> 5;

    float accum = 0.f;
    int   cur   = -1;
#pragma unroll
    for (int r = 0; r < 8; r++) {
        const int n = n0 + r;
        const int b = idx[n];
        float v = embnew[((long long)m * N_INST + n) * (NATT * DATT) + e];
        v = fmaxf(v, 0.f);
        const float p = expP[((long long)n * NMC + m) * NATT + k] /
                        seg [((long long)b * NMC + m) * NATT + k];
        v *= p;
        if (b != cur) {
            if (cur >= 0) atomicAdd(out + ((long long)cur * NMC + m) * (NATT * DATT) + e, accum);
            cur = b;
            accum = v;
        } else {
            accum += v;
        }
    }
    if (cur >= 0) atomicAdd(out + ((long long)cur * NMC + m) * (NATT * DATT) + e, accum);
}

// ---------------------------------------------------------------------------
__global__ void zero_kernel(float* __restrict__ out, float* __restrict__ seg)
{
    const int i = blockIdx.x * blockDim.x + threadIdx.x;
    if (i < BAGS * NMC * NATT * DATT) out[i] = 0.f;
    if (i < BAGS * NMC * NATT)        seg[i] = 0.f;
}

// ---------------------------------------------------------------------------
extern "C" void kernel_launch(void* const* d_in, const int* in_sizes, int n_in,
                              void* d_out, int out_size)
{
    const float* X      = (const float*)d_in[0];
    const int*   X_idx  = (const int*)  d_in[1];
    const float* Omega1 = (const float*)d_in[2];
    const float* Omega2 = (const float*)d_in[3];
    const float* W1     = (const float*)d_in[4];
    const float* b1     = (const float*)d_in[5];
    const float* W2     = (const float*)d_in[6];
    const float* b2     = (const float*)d_in[7];
    const float* Ws     = (const float*)d_in[8];
    const float* bs     = (const float*)d_in[9];
    const float* Wm     = (const float*)d_in[10];
    const float* bm     = (const float*)d_in[11];
    float* out = (float*)d_out;

    float *z, *phi, *h1, *emb, *expP, *seg;
    cudaGetSymbolAddress((void**)&z,    g_z);
    cudaGetSymbolAddress((void**)&phi,  g_phi);
    cudaGetSymbolAddress((void**)&h1,   g_h1);
    cudaGetSymbolAddress((void**)&emb,  g_emb);
    cudaGetSymbolAddress((void**)&expP, g_expP);
    cudaGetSymbolAddress((void**)&seg,  g_seg);

    // 0. zero accumulators
    zero_kernel<<<128, 256>>>(out, seg);

    // 1. z1[m] = X @ Omega1[m]                [16384,1024]x[1024,512] batched
    {
        dim3 g(RF / TBN, N_INST / TBM, NMC);
        tf32x3_gemm<<<g, 256>>>(X, Omega1, nullptr, z,
                                N_INST, RF, D0,
                                0LL, (long long)D0 * RF, (long long)N_INST * RF);
    }
    // 2. phi1 = LN(rf(z1))
    rfln_kernel<<<NMC * N_INST, 256>>>(z, phi);

    // 3. h1 = phi1 @ W1 + b1                  [65536,1024]x[1024,512]
    {
        dim3 g(D1 / TBN, (NMC * N_INST) / TBM, 1);
        tf32x3_gemm<<<g, 256>>>(phi, W1, b1, h1,
                                NMC * N_INST, D1, 2 * RF, 0LL, 0LL, 0LL);
    }
    // 4. z2[m] = h1[m] @ Omega2[m]            [16384,512]x[512,512] batched
    {
        dim3 g(RF / TBN, N_INST / TBM, NMC);
        tf32x3_gemm<<<g, 256>>>(h1, Omega2, nullptr, z,
                                N_INST, RF, D1,
                                (long long)N_INST * D1, (long long)D1 * RF,
                                (long long)N_INST * RF);
    }
    // 5. phi2 = LN(rf(z2))
    rfln_kernel<<<NMC * N_INST, 256>>>(z, phi);

    // 6. emb = phi2 @ W2 + b2                 [65536,1024]x[1024,256]
    {
        dim3 g(D2 / TBN, (NMC * N_INST) / TBM, 1);
        tf32x3_gemm<<<g, 256>>>(phi, W2, b2, emb,
                                NMC * N_INST, D2, 2 * RF, 0LL, 0LL, 0LL);
    }
    // 7. attention scores + segment exp-sums
    scores_kernel<<<(NMC * N_INST * 32 + 255) / 256, 256>>>(emb, Ws, bs, X_idx, expP, seg);

    // 8. emb_new = emb @ Wm + bm              [65536,256]x[256,128]
    {
        dim3 g((NATT * DATT) / TBN, (NMC * N_INST) / TBM, 1);
        tf32x3_gemm<<<g, 256>>>(emb, Wm, bm, z,
                                NMC * N_INST, NATT * DATT, D2, 0LL, 0LL, 0LL);
    }
    // 9. relu + softmax weighting + segment pooling
    pool_kernel<<<dim3(N_INST / 8, NMC), 128>>>(z, expP, seg, X_idx, out);
}

// round 3
// speedup vs baseline: 2.2546x; 1.6215x over previous
#include <cuda_runtime.h>
#include <cuda_bf16.h>
#include <math.h>
#include <stdint.h>

// Problem constants
#define N_INST 16384
#define BAGS   64
#define NMC    4
#define RF     512
#define D0     1024
#define D1     512
#define D2     256
#define NATT   4
#define DATT   32

typedef __nv_bfloat16 bf16;

// ---------------------------------------------------------------------------
// Scratch (static device globals: allocation-guard safe)
// ---------------------------------------------------------------------------
__device__ float g_z   [(size_t)NMC * N_INST * RF];        // z1 / z2 / emb_new
__device__ float g_emb [(size_t)NMC * N_INST * D2];        // fp32 emb (for scores)
__device__ float g_expP[(size_t)N_INST * NMC * NATT];
__device__ float g_seg [BAGS * NMC * NATT];

// bf16 hi/lo split operands
__device__ bf16 g_Xh  [(size_t)N_INST * D0];
__device__ bf16 g_Xl  [(size_t)N_INST * D0];
__device__ bf16 g_phih[(size_t)NMC * N_INST * 2 * RF];
__device__ bf16 g_phil[(size_t)NMC * N_INST * 2 * RF];
__device__ bf16 g_h1h [(size_t)NMC * N_INST * D1];
__device__ bf16 g_h1l [(size_t)NMC * N_INST * D1];
__device__ bf16 g_embh[(size_t)NMC * N_INST * D2];
__device__ bf16 g_embl[(size_t)NMC * N_INST * D2];
// transposed split weights [N][K] layout
__device__ bf16 g_O1Th[(size_t)NMC * RF * D0];
__device__ bf16 g_O1Tl[(size_t)NMC * RF * D0];
__device__ bf16 g_O2Th[(size_t)NMC * RF * D1];
__device__ bf16 g_O2Tl[(size_t)NMC * RF * D1];
__device__ bf16 g_W1Th[(size_t)D1 * 2 * RF];
__device__ bf16 g_W1Tl[(size_t)D1 * 2 * RF];
__device__ bf16 g_W2Th[(size_t)D2 * 2 * RF];
__device__ bf16 g_W2Tl[(size_t)D2 * 2 * RF];
__device__ bf16 g_WmTh[(size_t)(NATT * DATT) * D2];
__device__ bf16 g_WmTl[(size_t)(NATT * DATT) * D2];

// ---------------------------------------------------------------------------
// Helpers
// ---------------------------------------------------------------------------
__device__ __forceinline__ void bf16_split(float v, bf16& hi, bf16& lo) {
    hi = __float2bfloat16_rn(v);
    lo = __float2bfloat16_rn(v - __bfloat162float(hi));
}

#define CP_ASYNC16(smem_u32, gptr) \
    asm volatile("cp.async.cg.shared.global [%0], [%1], 16;\n" \
                 :: "r"(smem_u32), "l"(gptr))
#define CP_COMMIT()  asm volatile("cp.async.commit_group;\n")
#define CP_WAIT(n)   asm volatile("cp.async.wait_group %0;\n" :: "n"(n))

#define MMA_BF16(c, a, b) \
    asm volatile("mma.sync.aligned.m16n8k16.row.col.f32.bf16.bf16.f32 " \
                 "{%0,%1,%2,%3}, {%4,%5,%6,%7}, {%8,%9}, {%0,%1,%2,%3};" \
                 : "+f"((c)[0]), "+f"((c)[1]), "+f"((c)[2]), "+f"((c)[3]) \
                 : "r"((a)[0]), "r"((a)[1]), "r"((a)[2]), "r"((a)[3]), \
                   "r"((b)[0]), "r"((b)[1]))

// ---------------------------------------------------------------------------
// bf16x3 tensor-core GEMM: C[M,N] = (Ah+Al)[M,K] @ (Bh+Bl)[K,N] (+bias).
// A arrays are row-major [M][K] bf16; B arrays are TRANSPOSED [N][K] bf16.
// 3 MMA terms (hi*hi + lo*hi + hi*lo) -> ~1e-7 relative rounding.
// Block tile 128x128x32, 256 threads (8 warps), warp tile 32x64.
// No cvt in the mainloop: pure LDS + HMMA. Conflict-free 80B-stride smem.
// ---------------------------------------------------------------------------
#define TBM 128
#define TBN 128
#define TBK 32
#define LDK 40                       // smem row stride in bf16 (80 bytes)
#define TILE_ELEMS (128 * LDK)       // 5120 bf16 per tile
#define STAGE_ELEMS (4 * TILE_ELEMS) // Ah,Al,Bh,Bl
#define GEMM_SMEM_BYTES (2 * STAGE_ELEMS * 2)  // 81920

__global__ __launch_bounds__(256, 2) void bf16x3_gemm(
    const bf16* __restrict__ Ah, const bf16* __restrict__ Al,
    const bf16* __restrict__ BhT, const bf16* __restrict__ BlT,
    const float* __restrict__ bias,
    float* __restrict__ C, bf16* __restrict__ Chi, bf16* __restrict__ Clo,
    int M, int Ncols, int K,
    long long sA, long long sB, long long sC)
{
    Ah  += (long long)blockIdx.z * sA;  Al  += (long long)blockIdx.z * sA;
    BhT += (long long)blockIdx.z * sB;  BlT += (long long)blockIdx.z * sB;
    if (C)   C   += (long long)blockIdx.z * sC;
    if (Chi) { Chi += (long long)blockIdx.z * sC; Clo += (long long)blockIdx.z * sC; }

    extern __shared__ bf16 smem[];

    const int tid  = threadIdx.x;
    const int wid  = tid >> 5;
    const int lane = tid & 31;
    const int wm   = (wid >> 1) * 32;   // 4 warp-rows
    const int wn   = (wid & 1) * 64;    // 2 warp-cols
    const int brow = blockIdx.y * TBM;
    const int bcol = blockIdx.x * TBN;
    const int lg   = lane >> 2;         // 0..7
    const int lq2  = (lane & 3) * 2;    // 0,2,4,6

    float acc[2][8][4];
#pragma unroll
    for (int mi = 0; mi < 2; mi++)
#pragma unroll
        for (int ni = 0; ni < 8; ni++)
#pragma unroll
            for (int j = 0; j < 4; j++) acc[mi][ni][j] = 0.f;

    const int nStages = K / TBK;
    const uint32_t smemBase = (uint32_t)__cvta_generic_to_shared(smem);

    // staging: thread -> row = tid>>1, col half = (tid&1)*16 elems, i in {0,1} -> +8 elems
    const int stR  = tid >> 1;
    const int stC  = (tid & 1) * 16;

    // issue one full stage of cp.async into buffer `buf` for k-offset k0
#define STAGE_CPASYNC(buf, k0)                                                   \
    {                                                                            \
        const uint32_t sb = smemBase + (buf) * (STAGE_ELEMS * 2);                \
        _Pragma("unroll")                                                        \
        for (int i = 0; i < 2; i++) {                                            \
            const int c = stC + i * 8;                                           \
            CP_ASYNC16(sb + (0 * TILE_ELEMS + stR * LDK + c) * 2,                \
                       Ah + (long long)(brow + stR) * K + (k0) + c);             \
            CP_ASYNC16(sb + (1 * TILE_ELEMS + stR * LDK + c) * 2,                \
                       Al + (long long)(brow + stR) * K + (k0) + c);             \
            CP_ASYNC16(sb + (2 * TILE_ELEMS + stR * LDK + c) * 2,                \
                       BhT + (long long)(bcol + stR) * K + (k0) + c);            \
            CP_ASYNC16(sb + (3 * TILE_ELEMS + stR * LDK + c) * 2,                \
                       BlT + (long long)(bcol + stR) * K + (k0) + c);            \
        }                                                                        \
        CP_COMMIT();                                                             \
    }

    STAGE_CPASYNC(0, 0);

    for (int s = 0; s < nStages; s++) {
        const int buf = s & 1;
        if (s + 1 < nStages) {
            STAGE_CPASYNC(buf ^ 1, (s + 1) * TBK);
            CP_WAIT(1);
        } else {
            CP_WAIT(0);
        }
        __syncthreads();

        const bf16* __restrict__ Ahs = smem + buf * STAGE_ELEMS;
        const bf16* __restrict__ Als = Ahs + TILE_ELEMS;
        const bf16* __restrict__ Bhs = Ahs + 2 * TILE_ELEMS;
        const bf16* __restrict__ Bls = Ahs + 3 * TILE_ELEMS;

#pragma unroll
        for (int kk = 0; kk < 2; kk++) {
            const int k0 = kk * 16;
            uint32_t ah[2][4], al[2][4];
#pragma unroll
            for (int mi = 0; mi < 2; mi++) {
                const int r0 = (wm + mi * 16 + lg) * LDK + k0 + lq2;
                const int r1 = r0 + 8 * LDK;
                ah[mi][0] = *(const uint32_t*)(Ahs + r0);
                ah[mi][1] = *(const uint32_t*)(Ahs + r1);
                ah[mi][2] = *(const uint32_t*)(Ahs + r0 + 8);
                ah[mi][3] = *(const uint32_t*)(Ahs + r1 + 8);
                al[mi][0] = *(const uint32_t*)(Als + r0);
                al[mi][1] = *(const uint32_t*)(Als + r1);
                al[mi][2] = *(const uint32_t*)(Als + r0 + 8);
                al[mi][3] = *(const uint32_t*)(Als + r1 + 8);
            }
#pragma unroll
            for (int nh = 0; nh < 2; nh++) {
                uint32_t bh[4][2], bl[4][2];
#pragma unroll
                for (int j = 0; j < 4; j++) {
                    const int n = (wn + (nh * 4 + j) * 8 + lg) * LDK + k0 + lq2;
                    bh[j][0] = *(const uint32_t*)(Bhs + n);
                    bh[j][1] = *(const uint32_t*)(Bhs + n + 8);
                    bl[j][0] = *(const uint32_t*)(Bls + n);
                    bl[j][1] = *(const uint32_t*)(Bls + n + 8);
                }
#pragma unroll
                for (int mi = 0; mi < 2; mi++)
#pragma unroll
                    for (int j = 0; j < 4; j++) {
                        float* a = acc[mi][nh * 4 + j];
                        MMA_BF16(a, ah[mi], bh[j]);
                        MMA_BF16(a, al[mi], bh[j]);
                        MMA_BF16(a, ah[mi], bl[j]);
                    }
            }
        }
        __syncthreads();
    }

    // Epilogue
#pragma unroll
    for (int mi = 0; mi < 2; mi++) {
        const int row0 = brow + wm + mi * 16 + lg;
#pragma unroll
        for (int ni = 0; ni < 8; ni++) {
            const int col = bcol + wn + ni * 8 + lq2;
            float b0 = 0.f, b1 = 0.f;
            if (bias) { b0 = bias[col]; b1 = bias[col + 1]; }
            float v0 = acc[mi][ni][0] + b0;
            float v1 = acc[mi][ni][1] + b1;
            float v2 = acc[mi][ni][2] + b0;
            float v3 = acc[mi][ni][3] + b1;
            if (C) {
                *(float2*)(C + (long long)row0 * Ncols + col)       = make_float2(v0, v1);
                *(float2*)(C + (long long)(row0 + 8) * Ncols + col) = make_float2(v2, v3);
            }
            if (Chi) {
                bf16 h0, l0, h1_, l1, h2, l2, h3, l3;
                bf16_split(v0, h0, l0); bf16_split(v1, h1_, l1);
                bf16_split(v2, h2, l2); bf16_split(v3, h3, l3);
                *(__nv_bfloat162*)(Chi + (long long)row0 * Ncols + col)       = __nv_bfloat162(h0, h1_);
                *(__nv_bfloat162*)(Clo + (long long)row0 * Ncols + col)       = __nv_bfloat162(l0, l1);
                *(__nv_bfloat162*)(Chi + (long long)(row0 + 8) * Ncols + col) = __nv_bfloat162(h2, h3);
                *(__nv_bfloat162*)(Clo + (long long)(row0 + 8) * Ncols + col) = __nv_bfloat162(l2, l3);
            }
        }
    }
}

// ---------------------------------------------------------------------------
// Elementwise fp32 -> bf16 hi/lo split (same layout)
// ---------------------------------------------------------------------------
__global__ __launch_bounds__(256) void split_kernel(
    const float* __restrict__ src, bf16* __restrict__ hi, bf16* __restrict__ lo,
    long long n)
{
    long long i = (long long)blockIdx.x * blockDim.x + threadIdx.x;
    if (i < n) {
        bf16 h, l;
        bf16_split(src[i], h, l);
        hi[i] = h; lo[i] = l;
    }
}

// ---------------------------------------------------------------------------
// fp32 [K][N] -> transposed bf16 hi/lo [N][K] (batched over blockIdx.y)
// ---------------------------------------------------------------------------
__global__ __launch_bounds__(256) void splitT_kernel(
    const float* __restrict__ src, bf16* __restrict__ hiT, bf16* __restrict__ loT,
    int K, int N)
{
    const long long total = (long long)K * N;
    const long long boff  = (long long)blockIdx.y * total;
    long long t = (long long)blockIdx.x * blockDim.x + threadIdx.x;
    if (t < total) {
        const int k = (int)(t / N);
        const int n = (int)(t - (long long)k * N);
        bf16 h, l;
        bf16_split(src[boff + t], h, l);
        hiT[boff + (long long)n * K + k] = h;
        loT[boff + (long long)n * K + k] = l;
    }
}

// ---------------------------------------------------------------------------
// Fused RBF random features + LayerNorm; writes bf16 hi/lo phi directly.
// ---------------------------------------------------------------------------
__global__ __launch_bounds__(256) void rfln_kernel(
    const float* __restrict__ z, bf16* __restrict__ phih, bf16* __restrict__ phil)
{
    const long long row = blockIdx.x;
    const float* zr = z + row * RF;
    bf16* ph = phih + row * (2 * RF);
    bf16* pl = phil + row * (2 * RF);
    const int t = threadIdx.x;
    const float scale = 0.044194173824159216f;  // 1/sqrt(512)

    float za = zr[t];
    float zb = zr[t + 256];
    float ca = __cosf(za) * scale;
    float sa = __sinf(za) * scale;
    float cb = __cosf(zb) * scale;
    float sb = __sinf(zb) * scale;

    float sum = ca + cb + sa + sb;
    float sq  = ca * ca + cb * cb + sa * sa + sb * sb;

#pragma unroll
    for (int o = 16; o > 0; o >>= 1) {
        sum += __shfl_down_sync(0xffffffffu, sum, o);
        sq  += __shfl_down_sync(0xffffffffu, sq,  o);
    }
    __shared__ float s_sum[8], s_sq[8];
    __shared__ float s_mean, s_inv;
    const int warp = t >> 5, lane = t & 31;
    if (lane == 0) { s_sum[warp] = sum; s_sq[warp] = sq; }
    __syncthreads();
    if (t == 0) {
        float ts = 0.f, tq = 0.f;
#pragma unroll
        for (int i = 0; i < 8; i++) { ts += s_sum[i]; tq += s_sq[i]; }
        float mean = ts * (1.f / 1024.f);
        float var  = tq * (1.f / 1024.f) - mean * mean;
        s_mean = mean;
        s_inv  = rsqrtf(var + 1e-5f);
    }
    __syncthreads();
    const float mean = s_mean, inv = s_inv;
    bf16 h, l;
    bf16_split((ca - mean) * inv, h, l); ph[t]       = h; pl[t]       = l;
    bf16_split((cb - mean) * inv, h, l); ph[t + 256] = h; pl[t + 256] = l;
    bf16_split((sa - mean) * inv, h, l); ph[t + 512] = h; pl[t + 512] = l;
    bf16_split((sb - mean) * inv, h, l); ph[t + 768] = h; pl[t + 768] = l;
}

// ---------------------------------------------------------------------------
// Attention scores + per-bag exp-sum (atomics).
// ---------------------------------------------------------------------------
__global__ __launch_bounds__(256) void scores_kernel(
    const float* __restrict__ emb, const float* __restrict__ Ws,
    const float* __restrict__ bs, const int* __restrict__ idx,
    float* __restrict__ expP, float* __restrict__ seg)
{
    const int gw   = (blockIdx.x * blockDim.x + threadIdx.x) >> 5;
    const int lane = threadIdx.x & 31;
    if (gw >= NMC * N_INST) return;
    const int m = gw / N_INST;
    const int n = gw - m * N_INST;
    const float* e = emb + (long long)gw * D2;

    float a0 = 0.f, a1 = 0.f, a2 = 0.f, a3 = 0.f;
    for (int d = lane; d < D2; d += 32) {
        float  ev = e[d];
        float4 w4 = *(const float4*)(Ws + d * 4);
        a0 = fmaf(ev, w4.x, a0);
        a1 = fmaf(ev, w4.y, a1);
        a2 = fmaf(ev, w4.z, a2);
        a3 = fmaf(ev, w4.w, a3);
    }
#pragma unroll
    for (int o = 16; o > 0; o >>= 1) {
        a0 += __shfl_down_sync(0xffffffffu, a0, o);
        a1 += __shfl_down_sync(0xffffffffu, a1, o);
        a2 += __shfl_down_sync(0xffffffffu, a2, o);
        a3 += __shfl_down_sync(0xffffffffu, a3, o);
    }
    if (lane == 0) {
        const int b = idx[n];
        const float inv16 = 0.0625f;  // 1/sqrt(D2)
        float v0 = expf((a0 + bs[0]) * inv16);
        float v1 = expf((a1 + bs[1]) * inv16);
        float v2 = expf((a2 + bs[2]) * inv16);
        float v3 = expf((a3 + bs[3]) * inv16);
        float* ep = expP + ((long long)n * NMC + m) * NATT;
        ep[0] = v0; ep[1] = v1; ep[2] = v2; ep[3] = v3;
        float* sp = seg + ((long long)b * NMC + m) * NATT;
        atomicAdd(sp + 0, v0);
        atomicAdd(sp + 1, v1);
        atomicAdd(sp + 2, v2);
        atomicAdd(sp + 3, v3);
    }
}

// ---------------------------------------------------------------------------
// Weighted segment pooling.
// ---------------------------------------------------------------------------
__global__ __launch_bounds__(128) void pool_kernel(
    const float* __restrict__ embnew, const float* __restrict__ expP,
    const float* __restrict__ seg, const int* __restrict__ idx,
    float* __restrict__ out)
{
    const int m  = blockIdx.y;
    const int n0 = blockIdx.x * 8;
    const int e  = threadIdx.x;
    const int k  = e >> 5;

    float accum = 0.f;
    int   cur   = -1;
#pragma unroll
    for (int r = 0; r < 8; r++) {
        const int n = n0 + r;
        const int b = idx[n];
        float v = embnew[((long long)m * N_INST + n) * (NATT * DATT) + e];
        v = fmaxf(v, 0.f);
        const float p = expP[((long long)n * NMC + m) * NATT + k] /
                        seg [((long long)b * NMC + m) * NATT + k];
        v *= p;
        if (b != cur) {
            if (cur >= 0) atomicAdd(out + ((long long)cur * NMC + m) * (NATT * DATT) + e, accum);
            cur = b;
            accum = v;
        } else {
            accum += v;
        }
    }
    if (cur >= 0) atomicAdd(out + ((long long)cur * NMC + m) * (NATT * DATT) + e, accum);
}

// ---------------------------------------------------------------------------
__global__ void zero_kernel(float* __restrict__ out, float* __restrict__ seg)
{
    const int i = blockIdx.x * blockDim.x + threadIdx.x;
    if (i < BAGS * NMC * NATT * DATT) out[i] = 0.f;
    if (i < BAGS * NMC * NATT)        seg[i] = 0.f;
}

// ---------------------------------------------------------------------------
extern "C" void kernel_launch(void* const* d_in, const int* in_sizes, int n_in,
                              void* d_out, int out_size)
{
    const float* X      = (const float*)d_in[0];
    const int*   X_idx  = (const int*)  d_in[1];
    const float* Omega1 = (const float*)d_in[2];
    const float* Omega2 = (const float*)d_in[3];
    const float* W1     = (const float*)d_in[4];
    const float* b1     = (const float*)d_in[5];
    const float* W2     = (const float*)d_in[6];
    const float* b2     = (const float*)d_in[7];
    const float* Ws     = (const float*)d_in[8];
    const float* bs     = (const float*)d_in[9];
    const float* Wm     = (const float*)d_in[10];
    const float* bm     = (const float*)d_in[11];
    float* out = (float*)d_out;

    static bool cfg = false;
    if (!cfg) {
        cudaFuncSetAttribute(bf16x3_gemm,
                             cudaFuncAttributeMaxDynamicSharedMemorySize,
                             GEMM_SMEM_BYTES);
        cfg = true;
    }

    float *z, *emb, *expP, *seg;
    bf16 *Xh, *Xl, *phih, *phil, *h1h, *h1l, *embh, *embl;
    bf16 *O1Th, *O1Tl, *O2Th, *O2Tl, *W1Th, *W1Tl, *W2Th, *W2Tl, *WmTh, *WmTl;
    cudaGetSymbolAddress((void**)&z,    g_z);
    cudaGetSymbolAddress((void**)&emb,  g_emb);
    cudaGetSymbolAddress((void**)&expP, g_expP);
    cudaGetSymbolAddress((void**)&seg,  g_seg);
    cudaGetSymbolAddress((void**)&Xh,   g_Xh);
    cudaGetSymbolAddress((void**)&Xl,   g_Xl);
    cudaGetSymbolAddress((void**)&phih, g_phih);
    cudaGetSymbolAddress((void**)&phil, g_phil);
    cudaGetSymbolAddress((void**)&h1h,  g_h1h);
    cudaGetSymbolAddress((void**)&h1l,  g_h1l);
    cudaGetSymbolAddress((void**)&embh, g_embh);
    cudaGetSymbolAddress((void**)&embl, g_embl);
    cudaGetSymbolAddress((void**)&O1Th, g_O1Th);
    cudaGetSymbolAddress((void**)&O1Tl, g_O1Tl);
    cudaGetSymbolAddress((void**)&O2Th, g_O2Th);
    cudaGetSymbolAddress((void**)&O2Tl, g_O2Tl);
    cudaGetSymbolAddress((void**)&W1Th, g_W1Th);
    cudaGetSymbolAddress((void**)&W1Tl, g_W1Tl);
    cudaGetSymbolAddress((void**)&W2Th, g_W2Th);
    cudaGetSymbolAddress((void**)&W2Tl, g_W2Tl);
    cudaGetSymbolAddress((void**)&WmTh, g_WmTh);
    cudaGetSymbolAddress((void**)&WmTl, g_WmTl);

    // 0. zero accumulators + split inputs/weights
    zero_kernel<<<128, 256>>>(out, seg);
    {
        long long nX = (long long)N_INST * D0;
        split_kernel<<<(unsigned)((nX + 255) / 256), 256>>>(X, Xh, Xl, nX);
    }
    splitT_kernel<<<dim3((D0 * RF + 255) / 256, NMC), 256>>>(Omega1, O1Th, O1Tl, D0, RF);
    splitT_kernel<<<dim3((2 * RF * D1 + 255) / 256, 1), 256>>>(W1, W1Th, W1Tl, 2 * RF, D1);
    splitT_kernel<<<dim3((D1 * RF + 255) / 256, NMC), 256>>>(Omega2, O2Th, O2Tl, D1, RF);
    splitT_kernel<<<dim3((2 * RF * D2 + 255) / 256, 1), 256>>>(W2, W2Th, W2Tl, 2 * RF, D2);
    splitT_kernel<<<dim3((D2 * NATT * DATT + 255) / 256, 1), 256>>>(Wm, WmTh, WmTl, D2, NATT * DATT);

    // 1. z1[m] = X @ Omega1[m]   [16384,1024]x[1024,512] batched -> fp32 z
    {
        dim3 g(RF / TBN, N_INST / TBM, NMC);
        bf16x3_gemm<<<g, 256, GEMM_SMEM_BYTES>>>(
            Xh, Xl, O1Th, O1Tl, nullptr, z, nullptr, nullptr,
            N_INST, RF, D0,
            0LL, (long long)RF * D0, (long long)N_INST * RF);
    }
    // 2. phi1 = LN(rf(z1)) -> bf16 hi/lo
    rfln_kernel<<<NMC * N_INST, 256>>>(z, phih, phil);

    // 3. h1 = phi1 @ W1 + b1     [65536,1024]x[1024,512] -> bf16 hi/lo
    {
        dim3 g(D1 / TBN, (NMC * N_INST) / TBM, 1);
        bf16x3_gemm<<<g, 256, GEMM_SMEM_BYTES>>>(
            phih, phil, W1Th, W1Tl, b1, nullptr, h1h, h1l,
            NMC * N_INST, D1, 2 * RF, 0LL, 0LL, 0LL);
    }
    // 4. z2[m] = h1[m] @ Omega2[m]  [16384,512]x[512,512] batched -> fp32 z
    {
        dim3 g(RF / TBN, N_INST / TBM, NMC);
        bf16x3_gemm<<<g, 256, GEMM_SMEM_BYTES>>>(
            h1h, h1l, O2Th, O2Tl, nullptr, z, nullptr, nullptr,
            N_INST, RF, D1,
            (long long)N_INST * D1, (long long)RF * D1, (long long)N_INST * RF);
    }
    // 5. phi2 = LN(rf(z2)) -> bf16 hi/lo
    rfln_kernel<<<NMC * N_INST, 256>>>(z, phih, phil);

    // 6. emb = phi2 @ W2 + b2    [65536,1024]x[1024,256] -> fp32 + bf16 hi/lo
    {
        dim3 g(D2 / TBN, (NMC * N_INST) / TBM, 1);
        bf16x3_gemm<<<g, 256, GEMM_SMEM_BYTES>>>(
            phih, phil, W2Th, W2Tl, b2, emb, embh, embl,
            NMC * N_INST, D2, 2 * RF, 0LL, 0LL, 0LL);
    }
    // 7. attention scores + segment exp-sums
    scores_kernel<<<(NMC * N_INST * 32 + 255) / 256, 256>>>(emb, Ws, bs, X_idx, expP, seg);

    // 8. emb_new = emb @ Wm + bm [65536,256]x[256,128] -> fp32 into z
    {
        dim3 g((NATT * DATT) / TBN, (NMC * N_INST) / TBM, 1);
        bf16x3_gemm<<<g, 256, GEMM_SMEM_BYTES>>>(
            embh, embl, WmTh, WmTl, bm, z, nullptr, nullptr,
            NMC * N_INST, NATT * DATT, D2, 0LL, 0LL, 0LL);
    }
    // 9. relu + softmax weighting + segment pooling
    pool_kernel<<<dim3(N_INST / 8, NMC), 128>>>(z, expP, seg, X_idx, out);
}

// round 5
// speedup vs baseline: 2.4198x; 1.0733x over previous
#include <cuda_runtime.h>
#include <cuda_bf16.h>
#include <math.h>
#include <stdint.h>

// Problem constants
#define N_INST 16384
#define BAGS   64
#define NMC    4
#define RF     512
#define D0     1024
#define D1     512
#define D2     256
#define NATT   4
#define DATT   32

typedef __nv_bfloat16 bf16;

// ---------------------------------------------------------------------------
// Scratch (static device globals: allocation-guard safe)
// ---------------------------------------------------------------------------
__device__ float g_z   [(size_t)NMC * N_INST * RF];
__device__ float g_emb [(size_t)NMC * N_INST * D2];
__device__ float g_expP[(size_t)N_INST * NMC * NATT];
__device__ float g_seg [BAGS * NMC * NATT];

__device__ bf16 g_Xh  [(size_t)N_INST * D0];
__device__ bf16 g_Xl  [(size_t)N_INST * D0];
__device__ bf16 g_phih[(size_t)NMC * N_INST * 2 * RF];
__device__ bf16 g_phil[(size_t)NMC * N_INST * 2 * RF];
__device__ bf16 g_h1h [(size_t)NMC * N_INST * D1];
__device__ bf16 g_h1l [(size_t)NMC * N_INST * D1];
__device__ bf16 g_embh[(size_t)NMC * N_INST * D2];
__device__ bf16 g_embl[(size_t)NMC * N_INST * D2];
// transposed split weights [N][K]
__device__ bf16 g_O1Th[(size_t)NMC * RF * D0];
__device__ bf16 g_O1Tl[(size_t)NMC * RF * D0];
__device__ bf16 g_O2Th[(size_t)NMC * RF * D1];
__device__ bf16 g_O2Tl[(size_t)NMC * RF * D1];
__device__ bf16 g_W1Th[(size_t)D1 * 2 * RF];
__device__ bf16 g_W1Tl[(size_t)D1 * 2 * RF];
__device__ bf16 g_W2Th[(size_t)D2 * 2 * RF];
__device__ bf16 g_W2Tl[(size_t)D2 * 2 * RF];
__device__ bf16 g_WmTh[(size_t)(NATT * DATT) * D2];
__device__ bf16 g_WmTl[(size_t)(NATT * DATT) * D2];

// ---------------------------------------------------------------------------
// Helpers
// ---------------------------------------------------------------------------
__device__ __forceinline__ void bf16_split(float v, bf16& hi, bf16& lo) {
    hi = __float2bfloat16_rn(v);
    lo = __float2bfloat16_rn(v - __bfloat162float(hi));
}

#define CP_ASYNC16(smem_u32, gptr) \
    asm volatile("cp.async.cg.shared.global [%0], [%1], 16;\n" \
                 :: "r"(smem_u32), "l"(gptr))
#define CP_COMMIT()  asm volatile("cp.async.commit_group;\n")
#define CP_WAIT(n)   asm volatile("cp.async.wait_group %0;\n" :: "n"(n))

#define MMA_BF16(c, a0, a1, a2, a3, b0, b1) \
    asm volatile("mma.sync.aligned.m16n8k16.row.col.f32.bf16.bf16.f32 " \
                 "{%0,%1,%2,%3}, {%4,%5,%6,%7}, {%8,%9}, {%0,%1,%2,%3};" \
                 : "+f"((c)[0]), "+f"((c)[1]), "+f"((c)[2]), "+f"((c)[3]) \
                 : "r"(a0), "r"(a1), "r"(a2), "r"(a3), "r"(b0), "r"(b1))

#define LDSM4(r0, r1, r2, r3, addr) \
    asm volatile("ldmatrix.sync.aligned.m8n8.x4.shared.b16 {%0,%1,%2,%3}, [%4];" \
                 : "=r"(r0), "=r"(r1), "=r"(r2), "=r"(r3) : "r"(addr))

// ---------------------------------------------------------------------------
// bf16x3 tensor-core GEMM with ldmatrix fragment loads.
// C[M,N] = (Ah+Al)[M,K] @ (Bh+Bl)^T (+bias); B arrays are TRANSPOSED [N][K].
// 3 MMA terms (hi*hi + lo*hi + hi*lo) -> ~1e-7 relative rounding.
// Block tile 128x128x32, 256 threads (8 warps), warp tile 32x64.
// Mainloop = cp.async + LDSM + HMMA only. LDK=40 rows are conflict-free
// for both cp.async stores and ldmatrix reads.
// ---------------------------------------------------------------------------
#define TBM 128
#define TBN 128
#define TBK 32
#define LDK 40                       // smem row stride in bf16 (80 bytes)
#define TILE_ELEMS (128 * LDK)
#define STAGE_ELEMS (4 * TILE_ELEMS) // Ah,Al,Bh,Bl
#define GEMM_SMEM_BYTES (2 * STAGE_ELEMS * 2)  // 81920

__global__ __launch_bounds__(256, 2) void bf16x3_gemm(
    const bf16* __restrict__ Ah, const bf16* __restrict__ Al,
    const bf16* __restrict__ BhT, const bf16* __restrict__ BlT,
    const float* __restrict__ bias,
    float* __restrict__ C, bf16* __restrict__ Chi, bf16* __restrict__ Clo,
    int M, int Ncols, int K,
    long long sA, long long sB, long long sC)
{
    Ah  += (long long)blockIdx.z * sA;  Al  += (long long)blockIdx.z * sA;
    BhT += (long long)blockIdx.z * sB;  BlT += (long long)blockIdx.z * sB;
    if (C)   C   += (long long)blockIdx.z * sC;
    if (Chi) { Chi += (long long)blockIdx.z * sC; Clo += (long long)blockIdx.z * sC; }

    extern __shared__ bf16 smem[];

    const int tid  = threadIdx.x;
    const int wid  = tid >> 5;
    const int lane = tid & 31;
    const int wm   = (wid >> 1) * 32;   // 4 warp-rows
    const int wn   = (wid & 1) * 64;    // 2 warp-cols
    const int brow = blockIdx.y * TBM;
    const int bcol = blockIdx.x * TBN;
    const int lg   = lane >> 2;
    const int lq2  = (lane & 3) * 2;

    float acc[2][8][4];
#pragma unroll
    for (int mi = 0; mi < 2; mi++)
#pragma unroll
        for (int ni = 0; ni < 8; ni++)
#pragma unroll
            for (int j = 0; j < 4; j++) acc[mi][ni][j] = 0.f;

    const int nStages = K / TBK;
    const uint32_t smemBase = (uint32_t)__cvta_generic_to_shared(smem);

    // cp.async staging coords (one 128x32 tile = 256 x 16B chunks x 2)
    const int stR = tid >> 1;
    const int stC = (tid & 1) * 16;

#define STAGE_CPASYNC(buf, k0)                                                   \
    {                                                                            \
        const uint32_t sbb = smemBase + (buf) * (STAGE_ELEMS * 2);               \
        _Pragma("unroll")                                                        \
        for (int i = 0; i < 2; i++) {                                            \
            const int c = stC + i * 8;                                           \
            CP_ASYNC16(sbb + (0 * TILE_ELEMS + stR * LDK + c) * 2,               \
                       Ah + (long long)(brow + stR) * K + (k0) + c);             \
            CP_ASYNC16(sbb + (1 * TILE_ELEMS + stR * LDK + c) * 2,               \
                       Al + (long long)(brow + stR) * K + (k0) + c);             \
            CP_ASYNC16(sbb + (2 * TILE_ELEMS + stR * LDK + c) * 2,               \
                       BhT + (long long)(bcol + stR) * K + (k0) + c);            \
            CP_ASYNC16(sbb + (3 * TILE_ELEMS + stR * LDK + c) * 2,               \
                       BlT + (long long)(bcol + stR) * K + (k0) + c);            \
        }                                                                        \
        CP_COMMIT();                                                             \
    }

    // ldmatrix per-lane byte offsets (relative to tile base)
    // A x4: lanes 0-15 -> rows m..m+15 @k0 ; lanes 16-31 -> same rows @k0+8
    const uint32_t aOff =
        (uint32_t)(((lane & 15) * LDK + (lane >> 4) * 8) * 2);
    // B x4: m0 rows n..n+7 @k0, m1 same @k0+8, m2 rows n+8..n+15 @k0, m3 @k0+8
    const uint32_t bOff =
        (uint32_t)((((lane & 7) + ((lane >> 4) << 3)) * LDK +
                    (((lane >> 3) & 1) << 3)) * 2);

    STAGE_CPASYNC(0, 0);

    for (int s = 0; s < nStages; s++) {
        const int buf = s & 1;
        if (s + 1 < nStages) {
            STAGE_CPASYNC(buf ^ 1, (s + 1) * TBK);
            CP_WAIT(1);
        } else {
            CP_WAIT(0);
        }
        __syncthreads();

        const uint32_t tb  = smemBase + buf * (STAGE_ELEMS * 2);
        const uint32_t AhB = tb;
        const uint32_t AlB = tb + TILE_ELEMS * 2;
        const uint32_t BhB = tb + 2 * TILE_ELEMS * 2;
        const uint32_t BlB = tb + 3 * TILE_ELEMS * 2;

#pragma unroll
        for (int kk = 0; kk < 2; kk++) {
            const uint32_t kByte = kk * 16 * 2;
            uint32_t ah[2][4], al[2][4];
#pragma unroll
            for (int mi = 0; mi < 2; mi++) {
                const uint32_t rowB = (uint32_t)((wm + mi * 16) * LDK * 2);
                LDSM4(ah[mi][0], ah[mi][1], ah[mi][2], ah[mi][3],
                      AhB + rowB + aOff + kByte);
                LDSM4(al[mi][0], al[mi][1], al[mi][2], al[mi][3],
                      AlB + rowB + aOff + kByte);
            }
#pragma unroll
            for (int p = 0; p < 4; p++) {
                const uint32_t nB = (uint32_t)((wn + p * 16) * LDK * 2);
                uint32_t bh0, bh1, bh2, bh3, bl0, bl1, bl2, bl3;
                LDSM4(bh0, bh1, bh2, bh3, BhB + nB + bOff + kByte);
                LDSM4(bl0, bl1, bl2, bl3, BlB + nB + bOff + kByte);
#pragma unroll
                for (int mi = 0; mi < 2; mi++) {
                    float* c0 = acc[mi][p * 2];
                    float* c1 = acc[mi][p * 2 + 1];
                    MMA_BF16(c0, ah[mi][0], ah[mi][1], ah[mi][2], ah[mi][3], bh0, bh1);
                    MMA_BF16(c0, al[mi][0], al[mi][1], al[mi][2], al[mi][3], bh0, bh1);
                    MMA_BF16(c0, ah[mi][0], ah[mi][1], ah[mi][2], ah[mi][3], bl0, bl1);
                    MMA_BF16(c1, ah[mi][0], ah[mi][1], ah[mi][2], ah[mi][3], bh2, bh3);
                    MMA_BF16(c1, al[mi][0], al[mi][1], al[mi][2], al[mi][3], bh2, bh3);
                    MMA_BF16(c1, ah[mi][0], ah[mi][1], ah[mi][2], ah[mi][3], bl2, bl3);
                }
            }
        }
        __syncthreads();
    }

    // Epilogue (canonical m16n8 accumulator layout)
#pragma unroll
    for (int mi = 0; mi < 2; mi++) {
        const int row0 = brow + wm + mi * 16 + lg;
#pragma unroll
        for (int ni = 0; ni < 8; ni++) {
            const int col = bcol + wn + ni * 8 + lq2;
            float b0 = 0.f, b1 = 0.f;
            if (bias) { b0 = bias[col]; b1 = bias[col + 1]; }
            float v0 = acc[mi][ni][0] + b0;
            float v1 = acc[mi][ni][1] + b1;
            float v2 = acc[mi][ni][2] + b0;
            float v3 = acc[mi][ni][3] + b1;
            if (C) {
                *(float2*)(C + (long long)row0 * Ncols + col)       = make_float2(v0, v1);
                *(float2*)(C + (long long)(row0 + 8) * Ncols + col) = make_float2(v2, v3);
            }
            if (Chi) {
                bf16 h0, l0, h1, l1, h2, l2, h3, l3;
                bf16_split(v0, h0, l0); bf16_split(v1, h1, l1);
                bf16_split(v2, h2, l2); bf16_split(v3, h3, l3);
                *(__nv_bfloat162*)(Chi + (long long)row0 * Ncols + col)       = __nv_bfloat162(h0, h1);
                *(__nv_bfloat162*)(Clo + (long long)row0 * Ncols + col)       = __nv_bfloat162(l0, l1);
                *(__nv_bfloat162*)(Chi + (long long)(row0 + 8) * Ncols + col) = __nv_bfloat162(h2, h3);
                *(__nv_bfloat162*)(Clo + (long long)(row0 + 8) * Ncols + col) = __nv_bfloat162(l2, l3);
            }
        }
    }
}

// ---------------------------------------------------------------------------
// Elementwise fp32 -> bf16 hi/lo split
// ---------------------------------------------------------------------------
__global__ __launch_bounds__(256) void split_kernel(
    const float* __restrict__ src, bf16* __restrict__ hi, bf16* __restrict__ lo,
    long long n)
{
    long long i = (long long)blockIdx.x * blockDim.x + threadIdx.x;
    if (i < n) {
        bf16 h, l;
        bf16_split(src[i], h, l);
        hi[i] = h; lo[i] = l;
    }
}

// ---------------------------------------------------------------------------
// fp32 [K][N] -> transposed bf16 hi/lo [N][K], 32x32 smem-tiled (coalesced
// both directions). Grid: (K/32, N/32, batch), block (32, 8).
// ---------------------------------------------------------------------------
__global__ __launch_bounds__(256) void splitT_kernel(
    const float* __restrict__ src, bf16* __restrict__ hiT, bf16* __restrict__ loT,
    int K, int N)
{
    __shared__ float t[32][33];
    const long long boff = (long long)blockIdx.z * K * N;
    const int k0 = blockIdx.x * 32;
    const int n0 = blockIdx.y * 32;
    const int tx = threadIdx.x, ty = threadIdx.y;

#pragma unroll
    for (int i = 0; i < 32; i += 8)
        t[ty + i][tx] = src[boff + (long long)(k0 + ty + i) * N + n0 + tx];
    __syncthreads();
#pragma unroll
    for (int i = 0; i < 32; i += 8) {
        float v = t[tx][ty + i];
        bf16 h, l;
        bf16_split(v, h, l);
        hiT[boff + (long long)(n0 + ty + i) * K + k0 + tx] = h;
        loT[boff + (long long)(n0 + ty + i) * K + k0 + tx] = l;
    }
}

// ---------------------------------------------------------------------------
// Fused RBF random features + LayerNorm; writes bf16 hi/lo phi directly.
// ---------------------------------------------------------------------------
__global__ __launch_bounds__(256) void rfln_kernel(
    const float* __restrict__ z, bf16* __restrict__ phih, bf16* __restrict__ phil)
{
    const long long row = blockIdx.x;
    const float* zr = z + row * RF;
    bf16* ph = phih + row * (2 * RF);
    bf16* pl = phil + row * (2 * RF);
    const int t = threadIdx.x;
    const float scale = 0.044194173824159216f;  // 1/sqrt(512)

    float za = zr[t];
    float zb = zr[t + 256];
    float ca = __cosf(za) * scale;
    float sa = __sinf(za) * scale;
    float cb = __cosf(zb) * scale;
    float sb2 = __sinf(zb) * scale;

    float sum = ca + cb + sa + sb2;
    float sq  = ca * ca + cb * cb + sa * sa + sb2 * sb2;

#pragma unroll
    for (int o = 16; o > 0; o >>= 1) {
        sum += __shfl_down_sync(0xffffffffu, sum, o);
        sq  += __shfl_down_sync(0xffffffffu, sq,  o);
    }
    __shared__ float s_sum[8], s_sq[8];
    __shared__ float s_mean, s_inv;
    const int warp = t >> 5, lane = t & 31;
    if (lane == 0) { s_sum[warp] = sum; s_sq[warp] = sq; }
    __syncthreads();
    if (t == 0) {
        float ts = 0.f, tq = 0.f;
#pragma unroll
        for (int i = 0; i < 8; i++) { ts += s_sum[i]; tq += s_sq[i]; }
        float mean = ts * (1.f / 1024.f);
        float var  = tq * (1.f / 1024.f) - mean * mean;
        s_mean = mean;
        s_inv  = rsqrtf(var + 1e-5f);
    }
    __syncthreads();
    const float mean = s_mean, inv = s_inv;
    bf16 h, l;
    bf16_split((ca  - mean) * inv, h, l); ph[t]       = h; pl[t]       = l;
    bf16_split((cb  - mean) * inv, h, l); ph[t + 256] = h; pl[t + 256] = l;
    bf16_split((sa  - mean) * inv, h, l); ph[t + 512] = h; pl[t + 512] = l;
    bf16_split((sb2 - mean) * inv, h, l); ph[t + 768] = h; pl[t + 768] = l;
}

// ---------------------------------------------------------------------------
// Attention scores + per-bag exp-sum (atomics).
// ---------------------------------------------------------------------------
__global__ __launch_bounds__(256) void scores_kernel(
    const float* __restrict__ emb, const float* __restrict__ Ws,
    const float* __restrict__ bs, const int* __restrict__ idx,
    float* __restrict__ expP, float* __restrict__ seg)
{
    const int gw   = (blockIdx.x * blockDim.x + threadIdx.x) >> 5;
    const int lane = threadIdx.x & 31;
    if (gw >= NMC * N_INST) return;
    const int m = gw / N_INST;
    const int n = gw - m * N_INST;
    const float* e = emb + (long long)gw * D2;

    float a0 = 0.f, a1 = 0.f, a2 = 0.f, a3 = 0.f;
    for (int d = lane; d < D2; d += 32) {
        float  ev = e[d];
        float4 w4 = *(const float4*)(Ws + d * 4);
        a0 = fmaf(ev, w4.x, a0);
        a1 = fmaf(ev, w4.y, a1);
        a2 = fmaf(ev, w4.z, a2);
        a3 = fmaf(ev, w4.w, a3);
    }
#pragma unroll
    for (int o = 16; o > 0; o >>= 1) {
        a0 += __shfl_down_sync(0xffffffffu, a0, o);
        a1 += __shfl_down_sync(0xffffffffu, a1, o);
        a2 += __shfl_down_sync(0xffffffffu, a2, o);
        a3 += __shfl_down_sync(0xffffffffu, a3, o);
    }
    if (lane == 0) {
        const int b = idx[n];
        const float inv16 = 0.0625f;  // 1/sqrt(D2)
        float v0 = expf((a0 + bs[0]) * inv16);
        float v1 = expf((a1 + bs[1]) * inv16);
        float v2 = expf((a2 + bs[2]) * inv16);
        float v3 = expf((a3 + bs[3]) * inv16);
        float* ep = expP + ((long long)n * NMC + m) * NATT;
        ep[0] = v0; ep[1] = v1; ep[2] = v2; ep[3] = v3;
        float* sp = seg + ((long long)b * NMC + m) * NATT;
        atomicAdd(sp + 0, v0);
        atomicAdd(sp + 1, v1);
        atomicAdd(sp + 2, v2);
        atomicAdd(sp + 3, v3);
    }
}

// ---------------------------------------------------------------------------
// Weighted segment pooling.
// ---------------------------------------------------------------------------
__global__ __launch_bounds__(128) void pool_kernel(
    const float* __restrict__ embnew, const float* __restrict__ expP,
    const float* __restrict__ seg, const int* __restrict__ idx,
    float* __restrict__ out)
{
    const int m  = blockIdx.y;
    const int n0 = blockIdx.x * 8;
    const int e  = threadIdx.x;
    const int k  = e >> 5;

    float accum = 0.f;
    int   cur   = -1;
#pragma unroll
    for (int r = 0; r < 8; r++) {
        const int n = n0 + r;
        const int b = idx[n];
        float v = embnew[((long long)m * N_INST + n) * (NATT * DATT) + e];
        v = fmaxf(v, 0.f);
        const float p = expP[((long long)n * NMC + m) * NATT + k] /
                        seg [((long long)b * NMC + m) * NATT + k];
        v *= p;
        if (b != cur) {
            if (cur >= 0) atomicAdd(out + ((long long)cur * NMC + m) * (NATT * DATT) + e, accum);
            cur = b;
            accum = v;
        } else {
            accum += v;
        }
    }
    if (cur >= 0) atomicAdd(out + ((long long)cur * NMC + m) * (NATT * DATT) + e, accum);
}

// ---------------------------------------------------------------------------
__global__ void zero_kernel(float* __restrict__ out, float* __restrict__ seg)
{
    const int i = blockIdx.x * blockDim.x + threadIdx.x;
    if (i < BAGS * NMC * NATT * DATT) out[i] = 0.f;
    if (i < BAGS * NMC * NATT)        seg[i] = 0.f;
}

// ---------------------------------------------------------------------------
extern "C" void kernel_launch(void* const* d_in, const int* in_sizes, int n_in,
                              void* d_out, int out_size)
{
    const float* X      = (const float*)d_in[0];
    const int*   X_idx  = (const int*)  d_in[1];
    const float* Omega1 = (const float*)d_in[2];
    const float* Omega2 = (const float*)d_in[3];
    const float* W1     = (const float*)d_in[4];
    const float* b1     = (const float*)d_in[5];
    const float* W2     = (const float*)d_in[6];
    const float* b2     = (const float*)d_in[7];
    const float* Ws     = (const float*)d_in[8];
    const float* bs     = (const float*)d_in[9];
    const float* Wm     = (const float*)d_in[10];
    const float* bm     = (const float*)d_in[11];
    float* out = (float*)d_out;

    static bool cfg = false;
    if (!cfg) {
        cudaFuncSetAttribute(bf16x3_gemm,
                             cudaFuncAttributeMaxDynamicSharedMemorySize,
                             GEMM_SMEM_BYTES);
        cfg = true;
    }

    float *z, *emb, *expP, *seg;
    bf16 *Xh, *Xl, *phih, *phil, *h1h, *h1l, *embh, *embl;
    bf16 *O1Th, *O1Tl, *O2Th, *O2Tl, *W1Th, *W1Tl, *W2Th, *W2Tl, *WmTh, *WmTl;
    cudaGetSymbolAddress((void**)&z,    g_z);
    cudaGetSymbolAddress((void**)&emb,  g_emb);
    cudaGetSymbolAddress((void**)&expP, g_expP);
    cudaGetSymbolAddress((void**)&seg,  g_seg);
    cudaGetSymbolAddress((void**)&Xh,   g_Xh);
    cudaGetSymbolAddress((void**)&Xl,   g_Xl);
    cudaGetSymbolAddress((void**)&phih, g_phih);
    cudaGetSymbolAddress((void**)&phil, g_phil);
    cudaGetSymbolAddress((void**)&h1h,  g_h1h);
    cudaGetSymbolAddress((void**)&h1l,  g_h1l);
    cudaGetSymbolAddress((void**)&embh, g_embh);
    cudaGetSymbolAddress((void**)&embl, g_embl);
    cudaGetSymbolAddress((void**)&O1Th, g_O1Th);
    cudaGetSymbolAddress((void**)&O1Tl, g_O1Tl);
    cudaGetSymbolAddress((void**)&O2Th, g_O2Th);
    cudaGetSymbolAddress((void**)&O2Tl, g_O2Tl);
    cudaGetSymbolAddress((void**)&W1Th, g_W1Th);
    cudaGetSymbolAddress((void**)&W1Tl, g_W1Tl);
    cudaGetSymbolAddress((void**)&W2Th, g_W2Th);
    cudaGetSymbolAddress((void**)&W2Tl, g_W2Tl);
    cudaGetSymbolAddress((void**)&WmTh, g_WmTh);
    cudaGetSymbolAddress((void**)&WmTl, g_WmTl);

    // 0. zero accumulators + split inputs/weights (tiled transposes)
    zero_kernel<<<128, 256>>>(out, seg);
    {
        long long nX = (long long)N_INST * D0;
        split_kernel<<<(unsigned)((nX + 255) / 256), 256>>>(X, Xh, Xl, nX);
    }
    splitT_kernel<<<dim3(D0 / 32, RF / 32, NMC), dim3(32, 8)>>>(Omega1, O1Th, O1Tl, D0, RF);
    splitT_kernel<<<dim3((2 * RF) / 32, D1 / 32, 1), dim3(32, 8)>>>(W1, W1Th, W1Tl, 2 * RF, D1);
    splitT_kernel<<<dim3(D1 / 32, RF / 32, NMC), dim3(32, 8)>>>(Omega2, O2Th, O2Tl, D1, RF);
    splitT_kernel<<<dim3((2 * RF) / 32, D2 / 32, 1), dim3(32, 8)>>>(W2, W2Th, W2Tl, 2 * RF, D2);
    splitT_kernel<<<dim3(D2 / 32, (NATT * DATT) / 32, 1), dim3(32, 8)>>>(Wm, WmTh, WmTl, D2, NATT * DATT);

    // 1. z1[m] = X @ Omega1[m]   [16384,1024]x[1024,512] batched -> fp32 z
    {
        dim3 g(RF / TBN, N_INST / TBM, NMC);
        bf16x3_gemm<<<g, 256, GEMM_SMEM_BYTES>>>(
            Xh, Xl, O1Th, O1Tl, nullptr, z, nullptr, nullptr,
            N_INST, RF, D0,
            0LL, (long long)RF * D0, (long long)N_INST * RF);
    }
    // 2. phi1 = LN(rf(z1)) -> bf16 hi/lo
    rfln_kernel<<<NMC * N_INST, 256>>>(z, phih, phil);

    // 3. h1 = phi1 @ W1 + b1     [65536,1024]x[1024,512] -> bf16 hi/lo
    {
        dim3 g(D1 / TBN, (NMC * N_INST) / TBM, 1);
        bf16x3_gemm<<<g, 256, GEMM_SMEM_BYTES>>>(
            phih, phil, W1Th, W1Tl, b1, nullptr, h1h, h1l,
            NMC * N_INST, D1, 2 * RF, 0LL, 0LL, 0LL);
    }
    // 4. z2[m] = h1[m] @ Omega2[m]  [16384,512]x[512,512] batched -> fp32 z
    {
        dim3 g(RF / TBN, N_INST / TBM, NMC);
        bf16x3_gemm<<<g, 256, GEMM_SMEM_BYTES>>>(
            h1h, h1l, O2Th, O2Tl, nullptr, z, nullptr, nullptr,
            N_INST, RF, D1,
            (long long)N_INST * D1, (long long)RF * D1, (long long)N_INST * RF);
    }
    // 5. phi2 = LN(rf(z2)) -> bf16 hi/lo
    rfln_kernel<<<NMC * N_INST, 256>>>(z, phih, phil);

    // 6. emb = phi2 @ W2 + b2    [65536,1024]x[1024,256] -> fp32 + bf16 hi/lo
    {
        dim3 g(D2 / TBN, (NMC * N_INST) / TBM, 1);
        bf16x3_gemm<<<g, 256, GEMM_SMEM_BYTES>>>(
            phih, phil, W2Th, W2Tl, b2, emb, embh, embl,
            NMC * N_INST, D2, 2 * RF, 0LL, 0LL, 0LL);
    }
    // 7. attention scores + segment exp-sums
    scores_kernel<<<(NMC * N_INST * 32 + 255) / 256, 256>>>(emb, Ws, bs, X_idx, expP, seg);

    // 8. emb_new = emb @ Wm + bm [65536,256]x[256,128] -> fp32 into z
    {
        dim3 g((NATT * DATT) / TBN, (NMC * N_INST) / TBM, 1);
        bf16x3_gemm<<<g, 256, GEMM_SMEM_BYTES>>>(
            embh, embl, WmTh, WmTl, bm, z, nullptr, nullptr,
            NMC * N_INST, NATT * DATT, D2, 0LL, 0LL, 0LL);
    }
    // 9. relu + softmax weighting + segment pooling
    pool_kernel<<<dim3(N_INST / 8, NMC), 128>>>(z, expP, seg, X_idx, out);
}

// round 6
// speedup vs baseline: 3.2850x; 1.3575x over previous
#include <cuda_runtime.h>
#include <cuda_fp16.h>
#include <math.h>
#include <stdint.h>

// Problem constants
#define N_INST 16384
#define BAGS   64
#define NMC    4
#define RF     512
#define D0     1024
#define D1     512
#define D2     256
#define NATT   4
#define DATT   32

// ---------------------------------------------------------------------------
// Scratch (static device globals: allocation-guard safe)
// ---------------------------------------------------------------------------
__device__ float g_z   [(size_t)NMC * N_INST * RF];
__device__ float g_emb [(size_t)NMC * N_INST * D2];
__device__ float g_expP[(size_t)N_INST * NMC * NATT];
__device__ float g_seg [BAGS * NMC * NATT];

// fp16 A-side operands: hi/lo split (22-bit effective mantissa)
__device__ __half g_Xh  [(size_t)N_INST * D0];
__device__ __half g_Xl  [(size_t)N_INST * D0];
__device__ __half g_phih[(size_t)NMC * N_INST * 2 * RF];
__device__ __half g_phil[(size_t)NMC * N_INST * 2 * RF];
__device__ __half g_h1h [(size_t)NMC * N_INST * D1];
__device__ __half g_h1l [(size_t)NMC * N_INST * D1];
__device__ __half g_embh[(size_t)NMC * N_INST * D2];
__device__ __half g_embl[(size_t)NMC * N_INST * D2];
// fp16 B-side weights: single rn-rounded copy, TRANSPOSED [N][K]
__device__ __half g_O1T[(size_t)NMC * RF * D0];
__device__ __half g_O2T[(size_t)NMC * RF * D1];
__device__ __half g_W1T[(size_t)D1 * 2 * RF];
__device__ __half g_W2T[(size_t)D2 * 2 * RF];
__device__ __half g_WmT[(size_t)(NATT * DATT) * D2];

// ---------------------------------------------------------------------------
// Helpers
// ---------------------------------------------------------------------------
__device__ __forceinline__ void h_split(float v, __half& hi, __half& lo) {
    hi = __float2half_rn(v);
    lo = __float2half_rn(v - __half2float(hi));
}

#define CP_ASYNC16(smem_u32, gptr) \
    asm volatile("cp.async.cg.shared.global [%0], [%1], 16;\n" \
                 :: "r"(smem_u32), "l"(gptr))
#define CP_COMMIT()  asm volatile("cp.async.commit_group;\n")
#define CP_WAIT(n)   asm volatile("cp.async.wait_group %0;\n" :: "n"(n))

#define MMA_F16(c, a0, a1, a2, a3, b0, b1) \
    asm volatile("mma.sync.aligned.m16n8k16.row.col.f32.f16.f16.f32 " \
                 "{%0,%1,%2,%3}, {%4,%5,%6,%7}, {%8,%9}, {%0,%1,%2,%3};" \
                 : "+f"((c)[0]), "+f"((c)[1]), "+f"((c)[2]), "+f"((c)[3]) \
                 : "r"(a0), "r"(a1), "r"(a2), "r"(a3), "r"(b0), "r"(b1))

#define LDSM4(r0, r1, r2, r3, addr) \
    asm volatile("ldmatrix.sync.aligned.m8n8.x4.shared.b16 {%0,%1,%2,%3}, [%4];" \
                 : "=r"(r0), "=r"(r1), "=r"(r2), "=r"(r3) : "r"(addr))

// ---------------------------------------------------------------------------
// fp16x2 tensor-core GEMM: C[M,N] = (Ah+Al)[M,K] @ Bh^T (+bias).
// A split fp16 hi/lo (A to ~22 bits); B single fp16 rn. 2 MMA terms.
// B arrays are TRANSPOSED [N][K]. Block tile 128x128x32, 256 threads,
// warp tile 32x64. Mainloop = cp.async + LDSM + HMMA only.
// ---------------------------------------------------------------------------
#define TBM 128
#define TBN 128
#define TBK 32
#define LDK 40                       // smem row stride in halves (80 bytes)
#define TILE_ELEMS (128 * LDK)
#define STAGE_ELEMS (3 * TILE_ELEMS) // Ah, Al, Bh
#define GEMM_SMEM_BYTES (2 * STAGE_ELEMS * 2)  // 61440

__global__ __launch_bounds__(256, 2) void f16x2_gemm(
    const __half* __restrict__ Ah, const __half* __restrict__ Al,
    const __half* __restrict__ BhT,
    const float* __restrict__ bias,
    float* __restrict__ C, __half* __restrict__ Chi, __half* __restrict__ Clo,
    int M, int Ncols, int K,
    long long sA, long long sB, long long sC)
{
    Ah  += (long long)blockIdx.z * sA;  Al += (long long)blockIdx.z * sA;
    BhT += (long long)blockIdx.z * sB;
    if (C)   C   += (long long)blockIdx.z * sC;
    if (Chi) { Chi += (long long)blockIdx.z * sC; Clo += (long long)blockIdx.z * sC; }

    extern __shared__ __half smem[];

    const int tid  = threadIdx.x;
    const int wid  = tid >> 5;
    const int lane = tid & 31;
    const int wm   = (wid >> 1) * 32;   // 4 warp-rows
    const int wn   = (wid & 1) * 64;    // 2 warp-cols
    const int brow = blockIdx.y * TBM;
    const int bcol = blockIdx.x * TBN;
    const int lg   = lane >> 2;
    const int lq2  = (lane & 3) * 2;

    float acc[2][8][4];
#pragma unroll
    for (int mi = 0; mi < 2; mi++)
#pragma unroll
        for (int ni = 0; ni < 8; ni++)
#pragma unroll
            for (int j = 0; j < 4; j++) acc[mi][ni][j] = 0.f;

    const int nStages = K / TBK;
    const uint32_t smemBase = (uint32_t)__cvta_generic_to_shared(smem);

    // cp.async staging coords (one 128x32 tile = 512 x 16B chunks, 2/thread)
    const int stR = tid >> 1;
    const int stC = (tid & 1) * 16;

#define STAGE_CPASYNC(buf, k0)                                                   \
    {                                                                            \
        const uint32_t sbb = smemBase + (buf) * (STAGE_ELEMS * 2);               \
        _Pragma("unroll")                                                        \
        for (int i = 0; i < 2; i++) {                                            \
            const int c = stC + i * 8;                                           \
            CP_ASYNC16(sbb + (0 * TILE_ELEMS + stR * LDK + c) * 2,               \
                       Ah + (long long)(brow + stR) * K + (k0) + c);             \
            CP_ASYNC16(sbb + (1 * TILE_ELEMS + stR * LDK + c) * 2,               \
                       Al + (long long)(brow + stR) * K + (k0) + c);             \
            CP_ASYNC16(sbb + (2 * TILE_ELEMS + stR * LDK + c) * 2,               \
                       BhT + (long long)(bcol + stR) * K + (k0) + c);            \
        }                                                                        \
        CP_COMMIT();                                                             \
    }

    // ldmatrix per-lane byte offsets (relative to tile base)
    const uint32_t aOff =
        (uint32_t)(((lane & 15) * LDK + (lane >> 4) * 8) * 2);
    const uint32_t bOff =
        (uint32_t)((((lane & 7) + ((lane >> 4) << 3)) * LDK +
                    (((lane >> 3) & 1) << 3)) * 2);

    STAGE_CPASYNC(0, 0);

    for (int s = 0; s < nStages; s++) {
        const int buf = s & 1;
        if (s + 1 < nStages) {
            STAGE_CPASYNC(buf ^ 1, (s + 1) * TBK);
            CP_WAIT(1);
        } else {
            CP_WAIT(0);
        }
        __syncthreads();

        const uint32_t tb  = smemBase + buf * (STAGE_ELEMS * 2);
        const uint32_t AhB = tb;
        const uint32_t AlB = tb + TILE_ELEMS * 2;
        const uint32_t BhB = tb + 2 * TILE_ELEMS * 2;

#pragma unroll
        for (int kk = 0; kk < 2; kk++) {
            const uint32_t kByte = kk * 16 * 2;
            uint32_t ah[2][4], al[2][4];
#pragma unroll
            for (int mi = 0; mi < 2; mi++) {
                const uint32_t rowB = (uint32_t)((wm + mi * 16) * LDK * 2);
                LDSM4(ah[mi][0], ah[mi][1], ah[mi][2], ah[mi][3],
                      AhB + rowB + aOff + kByte);
                LDSM4(al[mi][0], al[mi][1], al[mi][2], al[mi][3],
                      AlB + rowB + aOff + kByte);
            }
#pragma unroll
            for (int p = 0; p < 4; p++) {
                const uint32_t nB = (uint32_t)((wn + p * 16) * LDK * 2);
                uint32_t bh0, bh1, bh2, bh3;
                LDSM4(bh0, bh1, bh2, bh3, BhB + nB + bOff + kByte);
#pragma unroll
                for (int mi = 0; mi < 2; mi++) {
                    float* c0 = acc[mi][p * 2];
                    float* c1 = acc[mi][p * 2 + 1];
                    MMA_F16(c0, ah[mi][0], ah[mi][1], ah[mi][2], ah[mi][3], bh0, bh1);
                    MMA_F16(c0, al[mi][0], al[mi][1], al[mi][2], al[mi][3], bh0, bh1);
                    MMA_F16(c1, ah[mi][0], ah[mi][1], ah[mi][2], ah[mi][3], bh2, bh3);
                    MMA_F16(c1, al[mi][0], al[mi][1], al[mi][2], al[mi][3], bh2, bh3);
                }
            }
        }
        __syncthreads();
    }

    // Epilogue (canonical m16n8 accumulator layout)
#pragma unroll
    for (int mi = 0; mi < 2; mi++) {
        const int row0 = brow + wm + mi * 16 + lg;
#pragma unroll
        for (int ni = 0; ni < 8; ni++) {
            const int col = bcol + wn + ni * 8 + lq2;
            float b0 = 0.f, b1 = 0.f;
            if (bias) { b0 = bias[col]; b1 = bias[col + 1]; }
            float v0 = acc[mi][ni][0] + b0;
            float v1 = acc[mi][ni][1] + b1;
            float v2 = acc[mi][ni][2] + b0;
            float v3 = acc[mi][ni][3] + b1;
            if (C) {
                *(float2*)(C + (long long)row0 * Ncols + col)       = make_float2(v0, v1);
                *(float2*)(C + (long long)(row0 + 8) * Ncols + col) = make_float2(v2, v3);
            }
            if (Chi) {
                __half h0, l0, h1, l1, h2, l2, h3, l3;
                h_split(v0, h0, l0); h_split(v1, h1, l1);
                h_split(v2, h2, l2); h_split(v3, h3, l3);
                *(__half2*)(Chi + (long long)row0 * Ncols + col)       = __halves2half2(h0, h1);
                *(__half2*)(Clo + (long long)row0 * Ncols + col)       = __halves2half2(l0, l1);
                *(__half2*)(Chi + (long long)(row0 + 8) * Ncols + col) = __halves2half2(h2, h3);
                *(__half2*)(Clo + (long long)(row0 + 8) * Ncols + col) = __halves2half2(l2, l3);
            }
        }
    }
}

// ---------------------------------------------------------------------------
// Elementwise fp32 -> fp16 hi/lo split
// ---------------------------------------------------------------------------
__global__ __launch_bounds__(256) void split_kernel(
    const float* __restrict__ src, __half* __restrict__ hi, __half* __restrict__ lo,
    long long n)
{
    long long i = (long long)blockIdx.x * blockDim.x + threadIdx.x;
    if (i < n) {
        __half h, l;
        h_split(src[i], h, l);
        hi[i] = h; lo[i] = l;
    }
}

// ---------------------------------------------------------------------------
// fp32 [K][N] -> transposed fp16 [N][K] (single rn), 32x32 smem-tiled.
// Grid: (K/32, N/32, batch), block (32, 8).
// ---------------------------------------------------------------------------
__global__ __launch_bounds__(256) void splitT_kernel(
    const float* __restrict__ src, __half* __restrict__ hT,
    int K, int N)
{
    __shared__ float t[32][33];
    const long long boff = (long long)blockIdx.z * K * N;
    const int k0 = blockIdx.x * 32;
    const int n0 = blockIdx.y * 32;
    const int tx = threadIdx.x, ty = threadIdx.y;

#pragma unroll
    for (int i = 0; i < 32; i += 8)
        t[ty + i][tx] = src[boff + (long long)(k0 + ty + i) * N + n0 + tx];
    __syncthreads();
#pragma unroll
    for (int i = 0; i < 32; i += 8)
        hT[boff + (long long)(n0 + ty + i) * K + k0 + tx] =
            __float2half_rn(t[tx][ty + i]);
}

// ---------------------------------------------------------------------------
// Fused RBF random features + LayerNorm; writes fp16 hi/lo phi directly.
// ---------------------------------------------------------------------------
__global__ __launch_bounds__(256) void rfln_kernel(
    const float* __restrict__ z, __half* __restrict__ phih, __half* __restrict__ phil)
{
    const long long row = blockIdx.x;
    const float* zr = z + row * RF;
    __half* ph = phih + row * (2 * RF);
    __half* pl = phil + row * (2 * RF);
    const int t = threadIdx.x;
    const float scale = 0.044194173824159216f;  // 1/sqrt(512)

    float za = zr[t];
    float zb = zr[t + 256];
    float ca = __cosf(za) * scale;
    float sa = __sinf(za) * scale;
    float cb = __cosf(zb) * scale;
    float sb2 = __sinf(zb) * scale;

    float sum = ca + cb + sa + sb2;
    float sq  = ca * ca + cb * cb + sa * sa + sb2 * sb2;

#pragma unroll
    for (int o = 16; o > 0; o >>= 1) {
        sum += __shfl_down_sync(0xffffffffu, sum, o);
        sq  += __shfl_down_sync(0xffffffffu, sq,  o);
    }
    __shared__ float s_sum[8], s_sq[8];
    __shared__ float s_mean, s_inv;
    const int warp = t >> 5, lane = t & 31;
    if (lane == 0) { s_sum[warp] = sum; s_sq[warp] = sq; }
    __syncthreads();
    if (t == 0) {
        float ts = 0.f, tq = 0.f;
#pragma unroll
        for (int i = 0; i < 8; i++) { ts += s_sum[i]; tq += s_sq[i]; }
        float mean = ts * (1.f / 1024.f);
        float var  = tq * (1.f / 1024.f) - mean * mean;
        s_mean = mean;
        s_inv  = rsqrtf(var + 1e-5f);
    }
    __syncthreads();
    const float mean = s_mean, inv = s_inv;
    __half h, l;
    h_split((ca  - mean) * inv, h, l); ph[t]       = h; pl[t]       = l;
    h_split((cb  - mean) * inv, h, l); ph[t + 256] = h; pl[t + 256] = l;
    h_split((sa  - mean) * inv, h, l); ph[t + 512] = h; pl[t + 512] = l;
    h_split((sb2 - mean) * inv, h, l); ph[t + 768] = h; pl[t + 768] = l;
}

// ---------------------------------------------------------------------------
// Attention scores + per-bag exp-sum (atomics).
// ---------------------------------------------------------------------------
__global__ __launch_bounds__(256) void scores_kernel(
    const float* __restrict__ emb, const float* __restrict__ Ws,
    const float* __restrict__ bs, const int* __restrict__ idx,
    float* __restrict__ expP, float* __restrict__ seg)
{
    const int gw   = (blockIdx.x * blockDim.x + threadIdx.x) >> 5;
    const int lane = threadIdx.x & 31;
    if (gw >= NMC * N_INST) return;
    const int m = gw / N_INST;
    const int n = gw - m * N_INST;
    const float* e = emb + (long long)gw * D2;

    float a0 = 0.f, a1 = 0.f, a2 = 0.f, a3 = 0.f;
    for (int d = lane; d < D2; d += 32) {
        float  ev = e[d];
        float4 w4 = *(const float4*)(Ws + d * 4);
        a0 = fmaf(ev, w4.x, a0);
        a1 = fmaf(ev, w4.y, a1);
        a2 = fmaf(ev, w4.z, a2);
        a3 = fmaf(ev, w4.w, a3);
    }
#pragma unroll
    for (int o = 16; o > 0; o >>= 1) {
        a0 += __shfl_down_sync(0xffffffffu, a0, o);
        a1 += __shfl_down_sync(0xffffffffu, a1, o);
        a2 += __shfl_down_sync(0xffffffffu, a2, o);
        a3 += __shfl_down_sync(0xffffffffu, a3, o);
    }
    if (lane == 0) {
        const int b = idx[n];
        const float inv16 = 0.0625f;  // 1/sqrt(D2)
        float v0 = expf((a0 + bs[0]) * inv16);
        float v1 = expf((a1 + bs[1]) * inv16);
        float v2 = expf((a2 + bs[2]) * inv16);
        float v3 = expf((a3 + bs[3]) * inv16);
        float* ep = expP + ((long long)n * NMC + m) * NATT;
        ep[0] = v0; ep[1] = v1; ep[2] = v2; ep[3] = v3;
        float* sp = seg + ((long long)b * NMC + m) * NATT;
        atomicAdd(sp + 0, v0);
        atomicAdd(sp + 1, v1);
        atomicAdd(sp + 2, v2);
        atomicAdd(sp + 3, v3);
    }
}

// ---------------------------------------------------------------------------
// Weighted segment pooling.
// ---------------------------------------------------------------------------
__global__ __launch_bounds__(128) void pool_kernel(
    const float* __restrict__ embnew, const float* __restrict__ expP,
    const float* __restrict__ seg, const int* __restrict__ idx,
    float* __restrict__ out)
{
    const int m  = blockIdx.y;
    const int n0 = blockIdx.x * 8;
    const int e  = threadIdx.x;
    const int k  = e >> 5;

    float accum = 0.f;
    int   cur   = -1;
#pragma unroll
    for (int r = 0; r < 8; r++) {
        const int n = n0 + r;
        const int b = idx[n];
        float v = embnew[((long long)m * N_INST + n) * (NATT * DATT) + e];
        v = fmaxf(v, 0.f);
        const float p = expP[((long long)n * NMC + m) * NATT + k] /
                        seg [((long long)b * NMC + m) * NATT + k];
        v *= p;
        if (b != cur) {
            if (cur >= 0) atomicAdd(out + ((long long)cur * NMC + m) * (NATT * DATT) + e, accum);
            cur = b;
            accum = v;
        } else {
            accum += v;
        }
    }
    if (cur >= 0) atomicAdd(out + ((long long)cur * NMC + m) * (NATT * DATT) + e, accum);
}

// ---------------------------------------------------------------------------
__global__ void zero_kernel(float* __restrict__ out, float* __restrict__ seg)
{
    const int i = blockIdx.x * blockDim.x + threadIdx.x;
    if (i < BAGS * NMC * NATT * DATT) out[i] = 0.f;
    if (i < BAGS * NMC * NATT)        seg[i] = 0.f;
}

// ---------------------------------------------------------------------------
extern "C" void kernel_launch(void* const* d_in, const int* in_sizes, int n_in,
                              void* d_out, int out_size)
{
    const float* X      = (const float*)d_in[0];
    const int*   X_idx  = (const int*)  d_in[1];
    const float* Omega1 = (const float*)d_in[2];
    const float* Omega2 = (const float*)d_in[3];
    const float* W1     = (const float*)d_in[4];
    const float* b1     = (const float*)d_in[5];
    const float* W2     = (const float*)d_in[6];
    const float* b2     = (const float*)d_in[7];
    const float* Ws     = (const float*)d_in[8];
    const float* bs     = (const float*)d_in[9];
    const float* Wm     = (const float*)d_in[10];
    const float* bm     = (const float*)d_in[11];
    float* out = (float*)d_out;

    static bool cfg = false;
    if (!cfg) {
        cudaFuncSetAttribute(f16x2_gemm,
                             cudaFuncAttributeMaxDynamicSharedMemorySize,
                             GEMM_SMEM_BYTES);
        cfg = true;
    }

    float *z, *emb, *expP, *seg;
    __half *Xh, *Xl, *phih, *phil, *h1h, *h1l, *embh, *embl;
    __half *O1T, *O2T, *W1T, *W2T, *WmT;
    cudaGetSymbolAddress((void**)&z,    g_z);
    cudaGetSymbolAddress((void**)&emb,  g_emb);
    cudaGetSymbolAddress((void**)&expP, g_expP);
    cudaGetSymbolAddress((void**)&seg,  g_seg);
    cudaGetSymbolAddress((void**)&Xh,   g_Xh);
    cudaGetSymbolAddress((void**)&Xl,   g_Xl);
    cudaGetSymbolAddress((void**)&phih, g_phih);
    cudaGetSymbolAddress((void**)&phil, g_phil);
    cudaGetSymbolAddress((void**)&h1h,  g_h1h);
    cudaGetSymbolAddress((void**)&h1l,  g_h1l);
    cudaGetSymbolAddress((void**)&embh, g_embh);
    cudaGetSymbolAddress((void**)&embl, g_embl);
    cudaGetSymbolAddress((void**)&O1T,  g_O1T);
    cudaGetSymbolAddress((void**)&O2T,  g_O2T);
    cudaGetSymbolAddress((void**)&W1T,  g_W1T);
    cudaGetSymbolAddress((void**)&W2T,  g_W2T);
    cudaGetSymbolAddress((void**)&WmT,  g_WmT);

    // 0. zero accumulators + split inputs / transpose-round weights
    zero_kernel<<<128, 256>>>(out, seg);
    {
        long long nX = (long long)N_INST * D0;
        split_kernel<<<(unsigned)((nX + 255) / 256), 256>>>(X, Xh, Xl, nX);
    }
    splitT_kernel<<<dim3(D0 / 32, RF / 32, NMC), dim3(32, 8)>>>(Omega1, O1T, D0, RF);
    splitT_kernel<<<dim3((2 * RF) / 32, D1 / 32, 1), dim3(32, 8)>>>(W1, W1T, 2 * RF, D1);
    splitT_kernel<<<dim3(D1 / 32, RF / 32, NMC), dim3(32, 8)>>>(Omega2, O2T, D1, RF);
    splitT_kernel<<<dim3((2 * RF) / 32, D2 / 32, 1), dim3(32, 8)>>>(W2, W2T, 2 * RF, D2);
    splitT_kernel<<<dim3(D2 / 32, (NATT * DATT) / 32, 1), dim3(32, 8)>>>(Wm, WmT, D2, NATT * DATT);

    // 1. z1[m] = X @ Omega1[m]   [16384,1024]x[1024,512] batched -> fp32 z
    {
        dim3 g(RF / TBN, N_INST / TBM, NMC);
        f16x2_gemm<<<g, 256, GEMM_SMEM_BYTES>>>(
            Xh, Xl, O1T, nullptr, z, nullptr, nullptr,
            N_INST, RF, D0,
            0LL, (long long)RF * D0, (long long)N_INST * RF);
    }
    // 2. phi1 = LN(rf(z1)) -> fp16 hi/lo
    rfln_kernel<<<NMC * N_INST, 256>>>(z, phih, phil);

    // 3. h1 = phi1 @ W1 + b1     [65536,1024]x[1024,512] -> fp16 hi/lo
    {
        dim3 g(D1 / TBN, (NMC * N_INST) / TBM, 1);
        f16x2_gemm<<<g, 256, GEMM_SMEM_BYTES>>>(
            phih, phil, W1T, b1, nullptr, h1h, h1l,
            NMC * N_INST, D1, 2 * RF, 0LL, 0LL, 0LL);
    }
    // 4. z2[m] = h1[m] @ Omega2[m]  [16384,512]x[512,512] batched -> fp32 z
    {
        dim3 g(RF / TBN, N_INST / TBM, NMC);
        f16x2_gemm<<<g, 256, GEMM_SMEM_BYTES>>>(
            h1h, h1l, O2T, nullptr, z, nullptr, nullptr,
            N_INST, RF, D1,
            (long long)N_INST * D1, (long long)RF * D1, (long long)N_INST * RF);
    }
    // 5. phi2 = LN(rf(z2)) -> fp16 hi/lo
    rfln_kernel<<<NMC * N_INST, 256>>>(z, phih, phil);

    // 6. emb = phi2 @ W2 + b2    [65536,1024]x[1024,256] -> fp32 + fp16 hi/lo
    {
        dim3 g(D2 / TBN, (NMC * N_INST) / TBM, 1);
        f16x2_gemm<<<g, 256, GEMM_SMEM_BYTES>>>(
            phih, phil, W2T, b2, emb, embh, embl,
            NMC * N_INST, D2, 2 * RF, 0LL, 0LL, 0LL);
    }
    // 7. attention scores + segment exp-sums
    scores_kernel<<<(NMC * N_INST * 32 + 255) / 256, 256>>>(emb, Ws, bs, X_idx, expP, seg);

    // 8. emb_new = emb @ Wm + bm [65536,256]x[256,128] -> fp32 into z
    {
        dim3 g((NATT * DATT) / TBN, (NMC * N_INST) / TBM, 1);
        f16x2_gemm<<<g, 256, GEMM_SMEM_BYTES>>>(
            embh, embl, WmT, bm, z, nullptr, nullptr,
            NMC * N_INST, NATT * DATT, D2, 0LL, 0LL, 0LL);
    }
    // 9. relu + softmax weighting + segment pooling
    pool_kernel<<<dim3(N_INST / 8, NMC), 128>>>(z, expP, seg, X_idx, out);
}

// round 7
// speedup vs baseline: 4.5710x; 1.3915x over previous
#include <cuda_runtime.h>
#include <cuda_fp16.h>
#include <math.h>
#include <stdint.h>

// Problem constants
#define N_INST 16384
#define BAGS   64
#define NMC    4
#define RF     512
#define D0     1024
#define D1     512
#define D2     256
#define NATT   4
#define DATT   32

// ---------------------------------------------------------------------------
// Scratch (static device globals: allocation-guard safe)
// ---------------------------------------------------------------------------
__device__ float g_z   [(size_t)NMC * N_INST * RF];
__device__ float g_emb [(size_t)NMC * N_INST * D2];
__device__ float g_expP[(size_t)N_INST * NMC * NATT];
__device__ float g_seg [BAGS * NMC * NATT];

__device__ __half g_Xh  [(size_t)N_INST * D0];
__device__ __half g_phih[(size_t)NMC * N_INST * 2 * RF];
__device__ __half g_h1h [(size_t)NMC * N_INST * D1];
__device__ __half g_embh[(size_t)NMC * N_INST * D2];
__device__ __half g_embl[(size_t)NMC * N_INST * D2];
// fp16 weights, TRANSPOSED [N][K]
__device__ __half g_O1T[(size_t)NMC * RF * D0];
__device__ __half g_O2T[(size_t)NMC * RF * D1];
__device__ __half g_W1T[(size_t)D1 * 2 * RF];
__device__ __half g_W2T[(size_t)D2 * 2 * RF];
__device__ __half g_WmT[(size_t)(NATT * DATT) * D2];

// ---------------------------------------------------------------------------
// Helpers
// ---------------------------------------------------------------------------
__device__ __forceinline__ void h_split(float v, __half& hi, __half& lo) {
    hi = __float2half_rn(v);
    lo = __float2half_rn(v - __half2float(hi));
}

#define CP_ASYNC16(smem_u32, gptr) \
    asm volatile("cp.async.cg.shared.global [%0], [%1], 16;\n" \
                 :: "r"(smem_u32), "l"(gptr))
#define CP_COMMIT()  asm volatile("cp.async.commit_group;\n")
#define CP_WAIT(n)   asm volatile("cp.async.wait_group %0;\n" :: "n"(n))

#define MMA_F16(c, a0, a1, a2, a3, b0, b1) \
    asm volatile("mma.sync.aligned.m16n8k16.row.col.f32.f16.f16.f32 " \
                 "{%0,%1,%2,%3}, {%4,%5,%6,%7}, {%8,%9}, {%0,%1,%2,%3};" \
                 : "+f"((c)[0]), "+f"((c)[1]), "+f"((c)[2]), "+f"((c)[3]) \
                 : "r"(a0), "r"(a1), "r"(a2), "r"(a3), "r"(b0), "r"(b1))

#define LDSM4(r0, r1, r2, r3, addr) \
    asm volatile("ldmatrix.sync.aligned.m8n8.x4.shared.b16 {%0,%1,%2,%3}, [%4];" \
                 : "=r"(r0), "=r"(r1), "=r"(r2), "=r"(r3) : "r"(addr))

// ---------------------------------------------------------------------------
// fp16 tensor-core GEMM, TERMS=1 (pure fp16) or TERMS=2 (A hi/lo split).
// C[M,N] = A[M,K] @ B^T (+bias); B TRANSPOSED [N][K].
// Block tile 128x128x32, 256 threads (8 warps), warp tile 32x64.
// Mainloop = cp.async + LDSM + HMMA only; LDK=40 rows conflict-free.
// ---------------------------------------------------------------------------
#define TBM 128
#define TBN 128
#define TBK 32
#define LDK 40
#define TILE_ELEMS (128 * LDK)

template<int TERMS>
__global__ __launch_bounds__(256, 2) void f16_gemm(
    const __half* __restrict__ Ah, const __half* __restrict__ Al,
    const __half* __restrict__ BhT,
    const float* __restrict__ bias,
    float* __restrict__ C, __half* __restrict__ Chi, __half* __restrict__ Clo,
    int M, int Ncols, int K,
    long long sA, long long sB, long long sC)
{
    constexpr int NT = TERMS + 1;            // tiles per stage: A(h[,l]), B
    constexpr int STAGE_ELEMS = NT * TILE_ELEMS;
    constexpr int B_TILE = TERMS;            // B tile index within stage

    Ah  += (long long)blockIdx.z * sA;
    if (TERMS == 2) Al += (long long)blockIdx.z * sA;
    BhT += (long long)blockIdx.z * sB;
    if (C)   C   += (long long)blockIdx.z * sC;
    if (Chi) Chi += (long long)blockIdx.z * sC;
    if (Clo) Clo += (long long)blockIdx.z * sC;

    extern __shared__ __half smem[];

    const int tid  = threadIdx.x;
    const int wid  = tid >> 5;
    const int lane = tid & 31;
    const int wm   = (wid >> 1) * 32;
    const int wn   = (wid & 1) * 64;
    const int brow = blockIdx.y * TBM;
    const int bcol = blockIdx.x * TBN;
    const int lg   = lane >> 2;
    const int lq2  = (lane & 3) * 2;

    float acc[2][8][4];
#pragma unroll
    for (int mi = 0; mi < 2; mi++)
#pragma unroll
        for (int ni = 0; ni < 8; ni++)
#pragma unroll
            for (int j = 0; j < 4; j++) acc[mi][ni][j] = 0.f;

    const int nStages = K / TBK;
    const uint32_t smemBase = (uint32_t)__cvta_generic_to_shared(smem);

    const int stR = tid >> 1;
    const int stC = (tid & 1) * 16;

    auto stage_cpasync = [&](int buf, int k0) {
        const uint32_t sbb = smemBase + buf * (STAGE_ELEMS * 2);
#pragma unroll
        for (int i = 0; i < 2; i++) {
            const int c = stC + i * 8;
            CP_ASYNC16(sbb + (0 * TILE_ELEMS + stR * LDK + c) * 2,
                       Ah + (long long)(brow + stR) * K + k0 + c);
            if (TERMS == 2)
                CP_ASYNC16(sbb + (1 * TILE_ELEMS + stR * LDK + c) * 2,
                           Al + (long long)(brow + stR) * K + k0 + c);
            CP_ASYNC16(sbb + (B_TILE * TILE_ELEMS + stR * LDK + c) * 2,
                       BhT + (long long)(bcol + stR) * K + k0 + c);
        }
        CP_COMMIT();
    };

    const uint32_t aOff =
        (uint32_t)(((lane & 15) * LDK + (lane >> 4) * 8) * 2);
    const uint32_t bOff =
        (uint32_t)((((lane & 7) + ((lane >> 4) << 3)) * LDK +
                    (((lane >> 3) & 1) << 3)) * 2);

    stage_cpasync(0, 0);

    for (int s = 0; s < nStages; s++) {
        const int buf = s & 1;
        if (s + 1 < nStages) {
            stage_cpasync(buf ^ 1, (s + 1) * TBK);
            CP_WAIT(1);
        } else {
            CP_WAIT(0);
        }
        __syncthreads();

        const uint32_t tb  = smemBase + buf * (STAGE_ELEMS * 2);
        const uint32_t AhB = tb;
        const uint32_t AlB = tb + TILE_ELEMS * 2;
        const uint32_t BhB = tb + B_TILE * TILE_ELEMS * 2;

#pragma unroll
        for (int kk = 0; kk < 2; kk++) {
            const uint32_t kByte = kk * 16 * 2;
            uint32_t ah[2][4], al[2][4];
#pragma unroll
            for (int mi = 0; mi < 2; mi++) {
                const uint32_t rowB = (uint32_t)((wm + mi * 16) * LDK * 2);
                LDSM4(ah[mi][0], ah[mi][1], ah[mi][2], ah[mi][3],
                      AhB + rowB + aOff + kByte);
                if (TERMS == 2)
                    LDSM4(al[mi][0], al[mi][1], al[mi][2], al[mi][3],
                          AlB + rowB + aOff + kByte);
            }
#pragma unroll
            for (int p = 0; p < 4; p++) {
                const uint32_t nB = (uint32_t)((wn + p * 16) * LDK * 2);
                uint32_t bh0, bh1, bh2, bh3;
                LDSM4(bh0, bh1, bh2, bh3, BhB + nB + bOff + kByte);
#pragma unroll
                for (int mi = 0; mi < 2; mi++) {
                    float* c0 = acc[mi][p * 2];
                    float* c1 = acc[mi][p * 2 + 1];
                    MMA_F16(c0, ah[mi][0], ah[mi][1], ah[mi][2], ah[mi][3], bh0, bh1);
                    MMA_F16(c1, ah[mi][0], ah[mi][1], ah[mi][2], ah[mi][3], bh2, bh3);
                    if (TERMS == 2) {
                        MMA_F16(c0, al[mi][0], al[mi][1], al[mi][2], al[mi][3], bh0, bh1);
                        MMA_F16(c1, al[mi][0], al[mi][1], al[mi][2], al[mi][3], bh2, bh3);
                    }
                }
            }
        }
        __syncthreads();
    }

    // Epilogue
#pragma unroll
    for (int mi = 0; mi < 2; mi++) {
        const int row0 = brow + wm + mi * 16 + lg;
#pragma unroll
        for (int ni = 0; ni < 8; ni++) {
            const int col = bcol + wn + ni * 8 + lq2;
            float b0 = 0.f, b1 = 0.f;
            if (bias) { b0 = bias[col]; b1 = bias[col + 1]; }
            float v0 = acc[mi][ni][0] + b0;
            float v1 = acc[mi][ni][1] + b1;
            float v2 = acc[mi][ni][2] + b0;
            float v3 = acc[mi][ni][3] + b1;
            if (C) {
                *(float2*)(C + (long long)row0 * Ncols + col)       = make_float2(v0, v1);
                *(float2*)(C + (long long)(row0 + 8) * Ncols + col) = make_float2(v2, v3);
            }
            if (Chi && !Clo) {
                *(__half2*)(Chi + (long long)row0 * Ncols + col) =
                    __halves2half2(__float2half_rn(v0), __float2half_rn(v1));
                *(__half2*)(Chi + (long long)(row0 + 8) * Ncols + col) =
                    __halves2half2(__float2half_rn(v2), __float2half_rn(v3));
            } else if (Chi) {
                __half h0, l0, h1, l1, h2, l2, h3, l3;
                h_split(v0, h0, l0); h_split(v1, h1, l1);
                h_split(v2, h2, l2); h_split(v3, h3, l3);
                *(__half2*)(Chi + (long long)row0 * Ncols + col)       = __halves2half2(h0, h1);
                *(__half2*)(Clo + (long long)row0 * Ncols + col)       = __halves2half2(l0, l1);
                *(__half2*)(Chi + (long long)(row0 + 8) * Ncols + col) = __halves2half2(h2, h3);
                *(__half2*)(Clo + (long long)(row0 + 8) * Ncols + col) = __halves2half2(l2, l3);
            }
        }
    }
}

#define SMEM_T1 (2 * 2 * TILE_ELEMS * 2 * 2 / 2)   // 2 bufs * 2 tiles * bytes = 40960
#define SMEM_T2 (2 * 3 * TILE_ELEMS * 2)           // 61440

// ---------------------------------------------------------------------------
// Elementwise fp32 -> fp16 (single rn)
// ---------------------------------------------------------------------------
__global__ __launch_bounds__(256) void cvt_kernel(
    const float* __restrict__ src, __half* __restrict__ dst, long long n)
{
    long long i = (long long)blockIdx.x * blockDim.x + threadIdx.x;
    if (i < n) dst[i] = __float2half_rn(src[i]);
}

// ---------------------------------------------------------------------------
// fp32 [K][N] -> transposed fp16 [N][K], 32x32 smem-tiled.
// ---------------------------------------------------------------------------
__global__ __launch_bounds__(256) void splitT_kernel(
    const float* __restrict__ src, __half* __restrict__ hT, int K, int N)
{
    __shared__ float t[32][33];
    const long long boff = (long long)blockIdx.z * K * N;
    const int k0 = blockIdx.x * 32;
    const int n0 = blockIdx.y * 32;
    const int tx = threadIdx.x, ty = threadIdx.y;

#pragma unroll
    for (int i = 0; i < 32; i += 8)
        t[ty + i][tx] = src[boff + (long long)(k0 + ty + i) * N + n0 + tx];
    __syncthreads();
#pragma unroll
    for (int i = 0; i < 32; i += 8)
        hT[boff + (long long)(n0 + ty + i) * K + k0 + tx] =
            __float2half_rn(t[tx][ty + i]);
}

// ---------------------------------------------------------------------------
// Fused RBF random features + LayerNorm; writes fp16 phi.
// ---------------------------------------------------------------------------
__global__ __launch_bounds__(256) void rfln_kernel(
    const float* __restrict__ z, __half* __restrict__ phih)
{
    const long long row = blockIdx.x;
    const float* zr = z + row * RF;
    __half* ph = phih + row * (2 * RF);
    const int t = threadIdx.x;
    const float scale = 0.044194173824159216f;  // 1/sqrt(512)

    float za = zr[t];
    float zb = zr[t + 256];
    float ca = __cosf(za) * scale;
    float sa = __sinf(za) * scale;
    float cb = __cosf(zb) * scale;
    float sb2 = __sinf(zb) * scale;

    float sum = ca + cb + sa + sb2;
    float sq  = ca * ca + cb * cb + sa * sa + sb2 * sb2;

#pragma unroll
    for (int o = 16; o > 0; o >>= 1) {
        sum += __shfl_down_sync(0xffffffffu, sum, o);
        sq  += __shfl_down_sync(0xffffffffu, sq,  o);
    }
    __shared__ float s_sum[8], s_sq[8];
    __shared__ float s_mean, s_inv;
    const int warp = t >> 5, lane = t & 31;
    if (lane == 0) { s_sum[warp] = sum; s_sq[warp] = sq; }
    __syncthreads();
    if (t == 0) {
        float ts = 0.f, tq = 0.f;
#pragma unroll
        for (int i = 0; i < 8; i++) { ts += s_sum[i]; tq += s_sq[i]; }
        float mean = ts * (1.f / 1024.f);
        float var  = tq * (1.f / 1024.f) - mean * mean;
        s_mean = mean;
        s_inv  = rsqrtf(var + 1e-5f);
    }
    __syncthreads();
    const float mean = s_mean, inv = s_inv;
    ph[t]       = __float2half_rn((ca  - mean) * inv);
    ph[t + 256] = __float2half_rn((cb  - mean) * inv);
    ph[t + 512] = __float2half_rn((sa  - mean) * inv);
    ph[t + 768] = __float2half_rn((sb2 - mean) * inv);
}

// ---------------------------------------------------------------------------
// Attention scores + per-bag exp-sum (atomics).
// ---------------------------------------------------------------------------
__global__ __launch_bounds__(256) void scores_kernel(
    const float* __restrict__ emb, const float* __restrict__ Ws,
    const float* __restrict__ bs, const int* __restrict__ idx,
    float* __restrict__ expP, float* __restrict__ seg)
{
    const int gw   = (blockIdx.x * blockDim.x + threadIdx.x) >> 5;
    const int lane = threadIdx.x & 31;
    if (gw >= NMC * N_INST) return;
    const int m = gw / N_INST;
    const int n = gw - m * N_INST;
    const float* e = emb + (long long)gw * D2;

    float a0 = 0.f, a1 = 0.f, a2 = 0.f, a3 = 0.f;
    for (int d = lane; d < D2; d += 32) {
        float  ev = e[d];
        float4 w4 = *(const float4*)(Ws + d * 4);
        a0 = fmaf(ev, w4.x, a0);
        a1 = fmaf(ev, w4.y, a1);
        a2 = fmaf(ev, w4.z, a2);
        a3 = fmaf(ev, w4.w, a3);
    }
#pragma unroll
    for (int o = 16; o > 0; o >>= 1) {
        a0 += __shfl_down_sync(0xffffffffu, a0, o);
        a1 += __shfl_down_sync(0xffffffffu, a1, o);
        a2 += __shfl_down_sync(0xffffffffu, a2, o);
        a3 += __shfl_down_sync(0xffffffffu, a3, o);
    }
    if (lane == 0) {
        const int b = idx[n];
        const float inv16 = 0.0625f;  // 1/sqrt(D2)
        float v0 = expf((a0 + bs[0]) * inv16);
        float v1 = expf((a1 + bs[1]) * inv16);
        float v2 = expf((a2 + bs[2]) * inv16);
        float v3 = expf((a3 + bs[3]) * inv16);
        float* ep = expP + ((long long)n * NMC + m) * NATT;
        ep[0] = v0; ep[1] = v1; ep[2] = v2; ep[3] = v3;
        float* sp = seg + ((long long)b * NMC + m) * NATT;
        atomicAdd(sp + 0, v0);
        atomicAdd(sp + 1, v1);
        atomicAdd(sp + 2, v2);
        atomicAdd(sp + 3, v3);
    }
}

// ---------------------------------------------------------------------------
// Weighted segment pooling.
// ---------------------------------------------------------------------------
__global__ __launch_bounds__(128) void pool_kernel(
    const float* __restrict__ embnew, const float* __restrict__ expP,
    const float* __restrict__ seg, const int* __restrict__ idx,
    float* __restrict__ out)
{
    const int m  = blockIdx.y;
    const int n0 = blockIdx.x * 8;
    const int e  = threadIdx.x;
    const int k  = e >> 5;

    float accum = 0.f;
    int   cur   = -1;
#pragma unroll
    for (int r = 0; r < 8; r++) {
        const int n = n0 + r;
        const int b = idx[n];
        float v = embnew[((long long)m * N_INST + n) * (NATT * DATT) + e];
        v = fmaxf(v, 0.f);
        const float p = expP[((long long)n * NMC + m) * NATT + k] /
                        seg [((long long)b * NMC + m) * NATT + k];
        v *= p;
        if (b != cur) {
            if (cur >= 0) atomicAdd(out + ((long long)cur * NMC + m) * (NATT * DATT) + e, accum);
            cur = b;
            accum = v;
        } else {
            accum += v;
        }
    }
    if (cur >= 0) atomicAdd(out + ((long long)cur * NMC + m) * (NATT * DATT) + e, accum);
}

// ---------------------------------------------------------------------------
__global__ void zero_kernel(float* __restrict__ out, float* __restrict__ seg)
{
    const int i = blockIdx.x * blockDim.x + threadIdx.x;
    if (i < BAGS * NMC * NATT * DATT) out[i] = 0.f;
    if (i < BAGS * NMC * NATT)        seg[i] = 0.f;
}

// ---------------------------------------------------------------------------
extern "C" void kernel_launch(void* const* d_in, const int* in_sizes, int n_in,
                              void* d_out, int out_size)
{
    const float* X      = (const float*)d_in[0];
    const int*   X_idx  = (const int*)  d_in[1];
    const float* Omega1 = (const float*)d_in[2];
    const float* Omega2 = (const float*)d_in[3];
    const float* W1     = (const float*)d_in[4];
    const float* b1     = (const float*)d_in[5];
    const float* W2     = (const float*)d_in[6];
    const float* b2     = (const float*)d_in[7];
    const float* Ws     = (const float*)d_in[8];
    const float* bs     = (const float*)d_in[9];
    const float* Wm     = (const float*)d_in[10];
    const float* bm     = (const float*)d_in[11];
    float* out = (float*)d_out;

    static bool cfg = false;
    if (!cfg) {
        cudaFuncSetAttribute(f16_gemm<1>,
                             cudaFuncAttributeMaxDynamicSharedMemorySize, SMEM_T1);
        cudaFuncSetAttribute(f16_gemm<2>,
                             cudaFuncAttributeMaxDynamicSharedMemorySize, SMEM_T2);
        cfg = true;
    }

    float *z, *emb, *expP, *seg;
    __half *Xh, *phih, *h1h, *embh, *embl;
    __half *O1T, *O2T, *W1T, *W2T, *WmT;
    cudaGetSymbolAddress((void**)&z,    g_z);
    cudaGetSymbolAddress((void**)&emb,  g_emb);
    cudaGetSymbolAddress((void**)&expP, g_expP);
    cudaGetSymbolAddress((void**)&seg,  g_seg);
    cudaGetSymbolAddress((void**)&Xh,   g_Xh);
    cudaGetSymbolAddress((void**)&phih, g_phih);
    cudaGetSymbolAddress((void**)&h1h,  g_h1h);
    cudaGetSymbolAddress((void**)&embh, g_embh);
    cudaGetSymbolAddress((void**)&embl, g_embl);
    cudaGetSymbolAddress((void**)&O1T,  g_O1T);
    cudaGetSymbolAddress((void**)&O2T,  g_O2T);
    cudaGetSymbolAddress((void**)&W1T,  g_W1T);
    cudaGetSymbolAddress((void**)&W2T,  g_W2T);
    cudaGetSymbolAddress((void**)&WmT,  g_WmT);

    // 0. zero accumulators + convert/transpose operands
    zero_kernel<<<128, 256>>>(out, seg);
    {
        long long nX = (long long)N_INST * D0;
        cvt_kernel<<<(unsigned)((nX + 255) / 256), 256>>>(X, Xh, nX);
    }
    splitT_kernel<<<dim3(D0 / 32, RF / 32, NMC), dim3(32, 8)>>>(Omega1, O1T, D0, RF);
    splitT_kernel<<<dim3((2 * RF) / 32, D1 / 32, 1), dim3(32, 8)>>>(W1, W1T, 2 * RF, D1);
    splitT_kernel<<<dim3(D1 / 32, RF / 32, NMC), dim3(32, 8)>>>(Omega2, O2T, D1, RF);
    splitT_kernel<<<dim3((2 * RF) / 32, D2 / 32, 1), dim3(32, 8)>>>(W2, W2T, 2 * RF, D2);
    splitT_kernel<<<dim3(D2 / 32, (NATT * DATT) / 32, 1), dim3(32, 8)>>>(Wm, WmT, D2, NATT * DATT);

    // 1. z1[m] = X @ Omega1[m]   [16384,1024]x[1024,512] batched -> fp32 z
    {
        dim3 g(RF / TBN, N_INST / TBM, NMC);
        f16_gemm<1><<<g, 256, SMEM_T1>>>(
            Xh, nullptr, O1T, nullptr, z, nullptr, nullptr,
            N_INST, RF, D0,
            0LL, (long long)RF * D0, (long long)N_INST * RF);
    }
    // 2. phi1 = LN(rf(z1)) -> fp16
    rfln_kernel<<<NMC * N_INST, 256>>>(z, phih);

    // 3. h1 = phi1 @ W1 + b1     [65536,1024]x[1024,512] -> fp16
    {
        dim3 g(D1 / TBN, (NMC * N_INST) / TBM, 1);
        f16_gemm<1><<<g, 256, SMEM_T1>>>(
            phih, nullptr, W1T, b1, nullptr, h1h, nullptr,
            NMC * N_INST, D1, 2 * RF, 0LL, 0LL, 0LL);
    }
    // 4. z2[m] = h1[m] @ Omega2[m]  [16384,512]x[512,512] batched -> fp32 z
    {
        dim3 g(RF / TBN, N_INST / TBM, NMC);
        f16_gemm<1><<<g, 256, SMEM_T1>>>(
            h1h, nullptr, O2T, nullptr, z, nullptr, nullptr,
            N_INST, RF, D1,
            (long long)N_INST * D1, (long long)RF * D1, (long long)N_INST * RF);
    }
    // 5. phi2 = LN(rf(z2)) -> fp16
    rfln_kernel<<<NMC * N_INST, 256>>>(z, phih);

    // 6. emb = phi2 @ W2 + b2    [65536,1024]x[1024,256] -> fp32 + fp16 hi/lo
    {
        dim3 g(D2 / TBN, (NMC * N_INST) / TBM, 1);
        f16_gemm<1><<<g, 256, SMEM_T1>>>(
            phih, nullptr, W2T, b2, emb, embh, embl,
            NMC * N_INST, D2, 2 * RF, 0LL, 0LL, 0LL);
    }
    // 7. attention scores + segment exp-sums
    scores_kernel<<<(NMC * N_INST * 32 + 255) / 256, 256>>>(emb, Ws, bs, X_idx, expP, seg);

    // 8. emb_new = emb @ Wm + bm [65536,256]x[256,128] (2-term A split) -> fp32 z
    {
        dim3 g((NATT * DATT) / TBN, (NMC * N_INST) / TBM, 1);
        f16_gemm<2><<<g, 256, SMEM_T2>>>(
            embh, embl, WmT, bm, z, nullptr, nullptr,
            NMC * N_INST, NATT * DATT, D2, 0LL, 0LL, 0LL);
    }
    // 9. relu + softmax weighting + segment pooling
    pool_kernel<<<dim3(N_INST / 8, NMC), 128>>>(z, expP, seg, X_idx, out);
}

// round 8
// speedup vs baseline: 4.7045x; 1.0292x over previous
#include <cuda_runtime.h>
#include <cuda_fp16.h>
#include <math.h>
#include <stdint.h>

// Problem constants
#define N_INST 16384
#define BAGS   64
#define NMC    4
#define RF     512
#define D0     1024
#define D1     512
#define D2     256
#define NATT   4
#define DATT   32

// ---------------------------------------------------------------------------
// Scratch (static device globals: allocation-guard safe)
// ---------------------------------------------------------------------------
__device__ float g_z   [(size_t)NMC * N_INST * RF];
__device__ float g_expP[(size_t)N_INST * NMC * NATT];
__device__ float g_seg [BAGS * NMC * NATT];

__device__ __half g_Xh  [(size_t)N_INST * D0];
__device__ __half g_phih[(size_t)NMC * N_INST * 2 * RF];
__device__ __half g_h1h [(size_t)NMC * N_INST * D1];
__device__ __half g_embh[(size_t)NMC * N_INST * D2];
__device__ __half g_embl[(size_t)NMC * N_INST * D2];
// fp16 weights, TRANSPOSED [N][K]
__device__ __half g_O1T[(size_t)NMC * RF * D0];
__device__ __half g_O2T[(size_t)NMC * RF * D1];
__device__ __half g_W1T[(size_t)D1 * 2 * RF];
__device__ __half g_W2T[(size_t)D2 * 2 * RF];
__device__ __half g_WmT[(size_t)(NATT * DATT) * D2];

// ---------------------------------------------------------------------------
// Helpers
// ---------------------------------------------------------------------------
__device__ __forceinline__ void h_split(float v, __half& hi, __half& lo) {
    hi = __float2half_rn(v);
    lo = __float2half_rn(v - __half2float(hi));
}

#define CP_ASYNC16(smem_u32, gptr) \
    asm volatile("cp.async.cg.shared.global [%0], [%1], 16;\n" \
                 :: "r"(smem_u32), "l"(gptr))
#define CP_COMMIT()  asm volatile("cp.async.commit_group;\n")
#define CP_WAIT(n)   asm volatile("cp.async.wait_group %0;\n" :: "n"(n))

#define MMA_F16(c, a0, a1, a2, a3, b0, b1) \
    asm volatile("mma.sync.aligned.m16n8k16.row.col.f32.f16.f16.f32 " \
                 "{%0,%1,%2,%3}, {%4,%5,%6,%7}, {%8,%9}, {%0,%1,%2,%3};" \
                 : "+f"((c)[0]), "+f"((c)[1]), "+f"((c)[2]), "+f"((c)[3]) \
                 : "r"(a0), "r"(a1), "r"(a2), "r"(a3), "r"(b0), "r"(b1))

#define LDSM4(r0, r1, r2, r3, addr) \
    asm volatile("ldmatrix.sync.aligned.m8n8.x4.shared.b16 {%0,%1,%2,%3}, [%4];" \
                 : "=r"(r0), "=r"(r1), "=r"(r2), "=r"(r3) : "r"(addr))

// ---------------------------------------------------------------------------
// fp16 tensor-core GEMM, TERMS=1 (pure fp16) or TERMS=2 (A hi/lo split).
// C[M,N] = A[M,K] @ B^T (+bias); B TRANSPOSED [N][K].
// Block tile 128x128x32, 256 threads, warp tile 32x64.
// 3-stage cp.async pipeline (prefetch 2 ahead); LDK=40 conflict-free.
// ---------------------------------------------------------------------------
#define TBM 128
#define TBN 128
#define TBK 32
#define LDK 40
#define TILE_ELEMS (128 * LDK)
#define NBUF 3

template<int TERMS>
__global__ __launch_bounds__(256, 2) void f16_gemm(
    const __half* __restrict__ Ah, const __half* __restrict__ Al,
    const __half* __restrict__ BhT,
    const float* __restrict__ bias,
    float* __restrict__ C, __half* __restrict__ Chi, __half* __restrict__ Clo,
    int M, int Ncols, int K,
    long long sA, long long sB, long long sC)
{
    constexpr int NT = TERMS + 1;            // tiles per stage: A(h[,l]), B
    constexpr int STAGE_ELEMS = NT * TILE_ELEMS;
    constexpr int B_TILE = TERMS;

    Ah  += (long long)blockIdx.z * sA;
    if (TERMS == 2) Al += (long long)blockIdx.z * sA;
    BhT += (long long)blockIdx.z * sB;
    if (C)   C   += (long long)blockIdx.z * sC;
    if (Chi) Chi += (long long)blockIdx.z * sC;
    if (Clo) Clo += (long long)blockIdx.z * sC;

    extern __shared__ __half smem[];

    const int tid  = threadIdx.x;
    const int wid  = tid >> 5;
    const int lane = tid & 31;
    const int wm   = (wid >> 1) * 32;
    const int wn   = (wid & 1) * 64;
    const int brow = blockIdx.y * TBM;
    const int bcol = blockIdx.x * TBN;
    const int lg   = lane >> 2;
    const int lq2  = (lane & 3) * 2;

    float acc[2][8][4];
#pragma unroll
    for (int mi = 0; mi < 2; mi++)
#pragma unroll
        for (int ni = 0; ni < 8; ni++)
#pragma unroll
            for (int j = 0; j < 4; j++) acc[mi][ni][j] = 0.f;

    const int nStages = K / TBK;
    const uint32_t smemBase = (uint32_t)__cvta_generic_to_shared(smem);

    const int stR = tid >> 1;
    const int stC = (tid & 1) * 16;

    auto stage_cpasync = [&](int buf, int k0) {
        const uint32_t sbb = smemBase + buf * (STAGE_ELEMS * 2);
#pragma unroll
        for (int i = 0; i < 2; i++) {
            const int c = stC + i * 8;
            CP_ASYNC16(sbb + (0 * TILE_ELEMS + stR * LDK + c) * 2,
                       Ah + (long long)(brow + stR) * K + k0 + c);
            if (TERMS == 2)
                CP_ASYNC16(sbb + (1 * TILE_ELEMS + stR * LDK + c) * 2,
                           Al + (long long)(brow + stR) * K + k0 + c);
            CP_ASYNC16(sbb + (B_TILE * TILE_ELEMS + stR * LDK + c) * 2,
                       BhT + (long long)(bcol + stR) * K + k0 + c);
        }
        CP_COMMIT();
    };

    const uint32_t aOff =
        (uint32_t)(((lane & 15) * LDK + (lane >> 4) * 8) * 2);
    const uint32_t bOff =
        (uint32_t)((((lane & 7) + ((lane >> 4) << 3)) * LDK +
                    (((lane >> 3) & 1) << 3)) * 2);

    stage_cpasync(0, 0);
    if (nStages > 1) stage_cpasync(1, TBK);

    int buf = 0;
    for (int s = 0; s < nStages; s++) {
        if (s + 2 < nStages) {
            stage_cpasync((s + 2) % NBUF, (s + 2) * TBK);
            CP_WAIT(2);
        } else if (s + 1 < nStages) {
            CP_WAIT(1);
        } else {
            CP_WAIT(0);
        }
        __syncthreads();

        const uint32_t tb  = smemBase + buf * (STAGE_ELEMS * 2);
        const uint32_t AhB = tb;
        const uint32_t AlB = tb + TILE_ELEMS * 2;
        const uint32_t BhB = tb + B_TILE * TILE_ELEMS * 2;

#pragma unroll
        for (int kk = 0; kk < 2; kk++) {
            const uint32_t kByte = kk * 16 * 2;
            uint32_t ah[2][4], al[2][4];
#pragma unroll
            for (int mi = 0; mi < 2; mi++) {
                const uint32_t rowB = (uint32_t)((wm + mi * 16) * LDK * 2);
                LDSM4(ah[mi][0], ah[mi][1], ah[mi][2], ah[mi][3],
                      AhB + rowB + aOff + kByte);
                if (TERMS == 2)
                    LDSM4(al[mi][0], al[mi][1], al[mi][2], al[mi][3],
                          AlB + rowB + aOff + kByte);
            }
#pragma unroll
            for (int p = 0; p < 4; p++) {
                const uint32_t nB = (uint32_t)((wn + p * 16) * LDK * 2);
                uint32_t bh0, bh1, bh2, bh3;
                LDSM4(bh0, bh1, bh2, bh3, BhB + nB + bOff + kByte);
#pragma unroll
                for (int mi = 0; mi < 2; mi++) {
                    float* c0 = acc[mi][p * 2];
                    float* c1 = acc[mi][p * 2 + 1];
                    MMA_F16(c0, ah[mi][0], ah[mi][1], ah[mi][2], ah[mi][3], bh0, bh1);
                    MMA_F16(c1, ah[mi][0], ah[mi][1], ah[mi][2], ah[mi][3], bh2, bh3);
                    if (TERMS == 2) {
                        MMA_F16(c0, al[mi][0], al[mi][1], al[mi][2], al[mi][3], bh0, bh1);
                        MMA_F16(c1, al[mi][0], al[mi][1], al[mi][2], al[mi][3], bh2, bh3);
                    }
                }
            }
        }
        __syncthreads();
        buf = (buf + 1 == NBUF) ? 0 : buf + 1;
    }

    // Epilogue
#pragma unroll
    for (int mi = 0; mi < 2; mi++) {
        const int row0 = brow + wm + mi * 16 + lg;
#pragma unroll
        for (int ni = 0; ni < 8; ni++) {
            const int col = bcol + wn + ni * 8 + lq2;
            float b0 = 0.f, b1 = 0.f;
            if (bias) { b0 = bias[col]; b1 = bias[col + 1]; }
            float v0 = acc[mi][ni][0] + b0;
            float v1 = acc[mi][ni][1] + b1;
            float v2 = acc[mi][ni][2] + b0;
            float v3 = acc[mi][ni][3] + b1;
            if (C) {
                *(float2*)(C + (long long)row0 * Ncols + col)       = make_float2(v0, v1);
                *(float2*)(C + (long long)(row0 + 8) * Ncols + col) = make_float2(v2, v3);
            }
            if (Chi && !Clo) {
                *(__half2*)(Chi + (long long)row0 * Ncols + col) =
                    __halves2half2(__float2half_rn(v0), __float2half_rn(v1));
                *(__half2*)(Chi + (long long)(row0 + 8) * Ncols + col) =
                    __halves2half2(__float2half_rn(v2), __float2half_rn(v3));
            } else if (Chi) {
                __half h0, l0, h1, l1, h2, l2, h3, l3;
                h_split(v0, h0, l0); h_split(v1, h1, l1);
                h_split(v2, h2, l2); h_split(v3, h3, l3);
                *(__half2*)(Chi + (long long)row0 * Ncols + col)       = __halves2half2(h0, h1);
                *(__half2*)(Clo + (long long)row0 * Ncols + col)       = __halves2half2(l0, l1);
                *(__half2*)(Chi + (long long)(row0 + 8) * Ncols + col) = __halves2half2(h2, h3);
                *(__half2*)(Clo + (long long)(row0 + 8) * Ncols + col) = __halves2half2(l2, l3);
            }
        }
    }
}

#define SMEM_T1 (NBUF * 2 * TILE_ELEMS * 2)   // 61440
#define SMEM_T2 (NBUF * 3 * TILE_ELEMS * 2)   // 92160

// ---------------------------------------------------------------------------
__global__ __launch_bounds__(256) void cvt_kernel(
    const float* __restrict__ src, __half* __restrict__ dst, long long n)
{
    long long i = (long long)blockIdx.x * blockDim.x + threadIdx.x;
    if (i < n) dst[i] = __float2half_rn(src[i]);
}

// fp32 [K][N] -> transposed fp16 [N][K], 32x32 smem-tiled.
__global__ __launch_bounds__(256) void splitT_kernel(
    const float* __restrict__ src, __half* __restrict__ hT, int K, int N)
{
    __shared__ float t[32][33];
    const long long boff = (long long)blockIdx.z * K * N;
    const int k0 = blockIdx.x * 32;
    const int n0 = blockIdx.y * 32;
    const int tx = threadIdx.x, ty = threadIdx.y;

#pragma unroll
    for (int i = 0; i < 32; i += 8)
        t[ty + i][tx] = src[boff + (long long)(k0 + ty + i) * N + n0 + tx];
    __syncthreads();
#pragma unroll
    for (int i = 0; i < 32; i += 8)
        hT[boff + (long long)(n0 + ty + i) * K + k0 + tx] =
            __float2half_rn(t[tx][ty + i]);
}

// ---------------------------------------------------------------------------
// Fused RBF random features + LayerNorm; writes fp16 phi.
// ---------------------------------------------------------------------------
__global__ __launch_bounds__(256) void rfln_kernel(
    const float* __restrict__ z, __half* __restrict__ phih)
{
    const long long row = blockIdx.x;
    const float* zr = z + row * RF;
    __half* ph = phih + row * (2 * RF);
    const int t = threadIdx.x;
    const float scale = 0.044194173824159216f;  // 1/sqrt(512)

    float za = zr[t];
    float zb = zr[t + 256];
    float ca = __cosf(za) * scale;
    float sa = __sinf(za) * scale;
    float cb = __cosf(zb) * scale;
    float sb2 = __sinf(zb) * scale;

    float sum = ca + cb + sa + sb2;
    float sq  = ca * ca + cb * cb + sa * sa + sb2 * sb2;

#pragma unroll
    for (int o = 16; o > 0; o >>= 1) {
        sum += __shfl_down_sync(0xffffffffu, sum, o);
        sq  += __shfl_down_sync(0xffffffffu, sq,  o);
    }
    __shared__ float s_sum[8], s_sq[8];
    __shared__ float s_mean, s_inv;
    const int warp = t >> 5, lane = t & 31;
    if (lane == 0) { s_sum[warp] = sum; s_sq[warp] = sq; }
    __syncthreads();
    if (t == 0) {
        float ts = 0.f, tq = 0.f;
#pragma unroll
        for (int i = 0; i < 8; i++) { ts += s_sum[i]; tq += s_sq[i]; }
        float mean = ts * (1.f / 1024.f);
        float var  = tq * (1.f / 1024.f) - mean * mean;
        s_mean = mean;
        s_inv  = rsqrtf(var + 1e-5f);
    }
    __syncthreads();
    const float mean = s_mean, inv = s_inv;
    ph[t]       = __float2half_rn((ca  - mean) * inv);
    ph[t + 256] = __float2half_rn((cb  - mean) * inv);
    ph[t + 512] = __float2half_rn((sa  - mean) * inv);
    ph[t + 768] = __float2half_rn((sb2 - mean) * inv);
}

// ---------------------------------------------------------------------------
// Attention scores from fp16 emb (hi part) + per-bag exp-sum (atomics).
// ---------------------------------------------------------------------------
__global__ __launch_bounds__(256) void scores_kernel(
    const __half* __restrict__ embh, const float* __restrict__ Ws,
    const float* __restrict__ bs, const int* __restrict__ idx,
    float* __restrict__ expP, float* __restrict__ seg)
{
    const int gw   = (blockIdx.x * blockDim.x + threadIdx.x) >> 5;
    const int lane = threadIdx.x & 31;
    if (gw >= NMC * N_INST) return;
    const int m = gw / N_INST;
    const int n = gw - m * N_INST;
    const __half2* e = (const __half2*)(embh + (long long)gw * D2);

    float a0 = 0.f, a1 = 0.f, a2 = 0.f, a3 = 0.f;
    for (int d = lane; d < D2 / 2; d += 32) {
        __half2 ev = e[d];
        float e0 = __low2float(ev), e1 = __high2float(ev);
        float4 w0 = *(const float4*)(Ws + (2 * d) * 4);
        float4 w1 = *(const float4*)(Ws + (2 * d + 1) * 4);
        a0 = fmaf(e0, w0.x, fmaf(e1, w1.x, a0));
        a1 = fmaf(e0, w0.y, fmaf(e1, w1.y, a1));
        a2 = fmaf(e0, w0.z, fmaf(e1, w1.z, a2));
        a3 = fmaf(e0, w0.w, fmaf(e1, w1.w, a3));
    }
#pragma unroll
    for (int o = 16; o > 0; o >>= 1) {
        a0 += __shfl_down_sync(0xffffffffu, a0, o);
        a1 += __shfl_down_sync(0xffffffffu, a1, o);
        a2 += __shfl_down_sync(0xffffffffu, a2, o);
        a3 += __shfl_down_sync(0xffffffffu, a3, o);
    }
    if (lane == 0) {
        const int b = idx[n];
        const float inv16 = 0.0625f;  // 1/sqrt(D2)
        float v0 = expf((a0 + bs[0]) * inv16);
        float v1 = expf((a1 + bs[1]) * inv16);
        float v2 = expf((a2 + bs[2]) * inv16);
        float v3 = expf((a3 + bs[3]) * inv16);
        float* ep = expP + ((long long)n * NMC + m) * NATT;
        ep[0] = v0; ep[1] = v1; ep[2] = v2; ep[3] = v3;
        float* sp = seg + ((long long)b * NMC + m) * NATT;
        atomicAdd(sp + 0, v0);
        atomicAdd(sp + 1, v1);
        atomicAdd(sp + 2, v2);
        atomicAdd(sp + 3, v3);
    }
}

// ---------------------------------------------------------------------------
// Weighted segment pooling.
// ---------------------------------------------------------------------------
__global__ __launch_bounds__(128) void pool_kernel(
    const float* __restrict__ embnew, const float* __restrict__ expP,
    const float* __restrict__ seg, const int* __restrict__ idx,
    float* __restrict__ out)
{
    const int m  = blockIdx.y;
    const int n0 = blockIdx.x * 8;
    const int e  = threadIdx.x;
    const int k  = e >> 5;

    float accum = 0.f;
    int   cur   = -1;
#pragma unroll
    for (int r = 0; r < 8; r++) {
        const int n = n0 + r;
        const int b = idx[n];
        float v = embnew[((long long)m * N_INST + n) * (NATT * DATT) + e];
        v = fmaxf(v, 0.f);
        const float p = expP[((long long)n * NMC + m) * NATT + k] /
                        seg [((long long)b * NMC + m) * NATT + k];
        v *= p;
        if (b != cur) {
            if (cur >= 0) atomicAdd(out + ((long long)cur * NMC + m) * (NATT * DATT) + e, accum);
            cur = b;
            accum = v;
        } else {
            accum += v;
        }
    }
    if (cur >= 0) atomicAdd(out + ((long long)cur * NMC + m) * (NATT * DATT) + e, accum);
}

// ---------------------------------------------------------------------------
__global__ void zero_kernel(float* __restrict__ out, float* __restrict__ seg)
{
    const int i = blockIdx.x * blockDim.x + threadIdx.x;
    if (i < BAGS * NMC * NATT * DATT) out[i] = 0.f;
    if (i < BAGS * NMC * NATT)        seg[i] = 0.f;
}

// ---------------------------------------------------------------------------
extern "C" void kernel_launch(void* const* d_in, const int* in_sizes, int n_in,
                              void* d_out, int out_size)
{
    const float* X      = (const float*)d_in[0];
    const int*   X_idx  = (const int*)  d_in[1];
    const float* Omega1 = (const float*)d_in[2];
    const float* Omega2 = (const float*)d_in[3];
    const float* W1     = (const float*)d_in[4];
    const float* b1     = (const float*)d_in[5];
    const float* W2     = (const float*)d_in[6];
    const float* b2     = (const float*)d_in[7];
    const float* Ws     = (const float*)d_in[8];
    const float* bs     = (const float*)d_in[9];
    const float* Wm     = (const float*)d_in[10];
    const float* bm     = (const float*)d_in[11];
    float* out = (float*)d_out;

    static bool cfg = false;
    if (!cfg) {
        cudaFuncSetAttribute(f16_gemm<1>,
                             cudaFuncAttributeMaxDynamicSharedMemorySize, SMEM_T1);
        cudaFuncSetAttribute(f16_gemm<2>,
                             cudaFuncAttributeMaxDynamicSharedMemorySize, SMEM_T2);
        cfg = true;
    }

    float *z, *expP, *seg;
    __half *Xh, *phih, *h1h, *embh, *embl;
    __half *O1T, *O2T, *W1T, *W2T, *WmT;
    cudaGetSymbolAddress((void**)&z,    g_z);
    cudaGetSymbolAddress((void**)&expP, g_expP);
    cudaGetSymbolAddress((void**)&seg,  g_seg);
    cudaGetSymbolAddress((void**)&Xh,   g_Xh);
    cudaGetSymbolAddress((void**)&phih, g_phih);
    cudaGetSymbolAddress((void**)&h1h,  g_h1h);
    cudaGetSymbolAddress((void**)&embh, g_embh);
    cudaGetSymbolAddress((void**)&embl, g_embl);
    cudaGetSymbolAddress((void**)&O1T,  g_O1T);
    cudaGetSymbolAddress((void**)&O2T,  g_O2T);
    cudaGetSymbolAddress((void**)&W1T,  g_W1T);
    cudaGetSymbolAddress((void**)&W2T,  g_W2T);
    cudaGetSymbolAddress((void**)&WmT,  g_WmT);

    // Launch order arranged so the 6th launch (ncu -s 5 -c 1) is GEMM1.
    // 1. zero
    zero_kernel<<<128, 256>>>(out, seg);
    // 2. X -> fp16
    {
        long long nX = (long long)N_INST * D0;
        cvt_kernel<<<(unsigned)((nX + 255) / 256), 256>>>(X, Xh, nX);
    }
    // 3-5. weight transposes needed before GEMM1 (+ two fillers)
    splitT_kernel<<<dim3(D0 / 32, RF / 32, NMC), dim3(32, 8)>>>(Omega1, O1T, D0, RF);
    splitT_kernel<<<dim3((2 * RF) / 32, D1 / 32, 1), dim3(32, 8)>>>(W1, W1T, 2 * RF, D1);
    splitT_kernel<<<dim3(D1 / 32, RF / 32, NMC), dim3(32, 8)>>>(Omega2, O2T, D1, RF);

    // 6. z1[m] = X @ Omega1[m]  [16384,1024]x[1024,512] batched  <-- PROFILED
    {
        dim3 g(RF / TBN, N_INST / TBM, NMC);
        f16_gemm<1><<<g, 256, SMEM_T1>>>(
            Xh, nullptr, O1T, nullptr, z, nullptr, nullptr,
            N_INST, RF, D0,
            0LL, (long long)RF * D0, (long long)N_INST * RF);
    }
    // 7-8. remaining weight transposes
    splitT_kernel<<<dim3((2 * RF) / 32, D2 / 32, 1), dim3(32, 8)>>>(W2, W2T, 2 * RF, D2);
    splitT_kernel<<<dim3(D2 / 32, (NATT * DATT) / 32, 1), dim3(32, 8)>>>(Wm, WmT, D2, NATT * DATT);

    // 9. phi1 = LN(rf(z1))
    rfln_kernel<<<NMC * N_INST, 256>>>(z, phih);

    // 10. h1 = phi1 @ W1 + b1
    {
        dim3 g(D1 / TBN, (NMC * N_INST) / TBM, 1);
        f16_gemm<1><<<g, 256, SMEM_T1>>>(
            phih, nullptr, W1T, b1, nullptr, h1h, nullptr,
            NMC * N_INST, D1, 2 * RF, 0LL, 0LL, 0LL);
    }
    // 11. z2[m] = h1[m] @ Omega2[m]
    {
        dim3 g(RF / TBN, N_INST / TBM, NMC);
        f16_gemm<1><<<g, 256, SMEM_T1>>>(
            h1h, nullptr, O2T, nullptr, z, nullptr, nullptr,
            N_INST, RF, D1,
            (long long)N_INST * D1, (long long)RF * D1, (long long)N_INST * RF);
    }
    // 12. phi2 = LN(rf(z2))
    rfln_kernel<<<NMC * N_INST, 256>>>(z, phih);

    // 13. emb = phi2 @ W2 + b2  -> fp16 hi/lo only
    {
        dim3 g(D2 / TBN, (NMC * N_INST) / TBM, 1);
        f16_gemm<1><<<g, 256, SMEM_T1>>>(
            phih, nullptr, W2T, b2, nullptr, embh, embl,
            NMC * N_INST, D2, 2 * RF, 0LL, 0LL, 0LL);
    }
    // 14. attention scores + segment exp-sums (reads fp16 embh)
    scores_kernel<<<(NMC * N_INST * 32 + 255) / 256, 256>>>(embh, Ws, bs, X_idx, expP, seg);

    // 15. emb_new = emb @ Wm + bm (2-term A split) -> fp32 z
    {
        dim3 g((NATT * DATT) / TBN, (NMC * N_INST) / TBM, 1);
        f16_gemm<2><<<g, 256, SMEM_T2>>>(
            embh, embl, WmT, bm, z, nullptr, nullptr,
            NMC * N_INST, NATT * DATT, D2, 0LL, 0LL, 0LL);
    }
    // 16. relu + softmax weighting + segment pooling
    pool_kernel<<<dim3(N_INST / 8, NMC), 128>>>(z, expP, seg, X_idx, out);
}